// round 6
// baseline (speedup 1.0000x reference)
#include <cuda_runtime.h>
#include <cuda_bf16.h>
#include <cstdint>
#include <math.h>

#define NMAX   25000
#define EMAX   400000
#define GMAX   1000
#define HID    185
#define INCH   9
#define LDAH   768      // padded concat width (4*192)
#define LDT    186      // tmp row stride (even -> float2-aligned)

// ---------------- scratch ----------------
__device__ int      g_cnt[NMAX];          // BSS zero at load; self-cleaned each call
__device__ int      g_part[NMAX];
__device__ int      g_bsum[128];
__device__ int      g_offs[NMAX + 1];
__device__ int      g_cursor[NMAX];
__device__ float    g_dis[NMAX];
__device__ __align__(16) int2 g_csr[EMAX];   // (src, weight bits)
__device__ __align__(16) __nv_bfloat16 g_A0h[NMAX * 64];
__device__ __align__(16) __nv_bfloat16 g_A0l[NMAX * 64];
__device__ __align__(16) __nv_bfloat16 g_Ah[NMAX * LDAH];
__device__ __align__(16) __nv_bfloat16 g_Al[NMAX * LDAH];
__device__ __align__(16) __nv_bfloat16 g_W0th[192 * 64];
__device__ __align__(16) __nv_bfloat16 g_W0tl[192 * 64];
__device__ __align__(16) __nv_bfloat16 g_Whth[3 * 192 * 192];
__device__ __align__(16) __nv_bfloat16 g_Whtl[3 * 192 * 192];
__device__ __align__(16) __nv_bfloat16 g_Wjkth[192 * 768];
__device__ __align__(16) __nv_bfloat16 g_Wjktl[192 * 768];
__device__ __align__(16) float g_tmp[NMAX * LDT];
__device__ unsigned g_pool[GMAX * HID];
__device__ float    g_bnscale[4 * HID];
__device__ float    g_bnshift[4 * HID];

// ---------------- helpers ----------------
__device__ __forceinline__ unsigned enc_f(float f) {
    unsigned u = __float_as_uint(f);
    return (u & 0x80000000u) ? ~u : (u | 0x80000000u);
}
__device__ __forceinline__ float dec_f(unsigned e) {
    return (e & 0x80000000u) ? __uint_as_float(e & 0x7FFFFFFFu) : __uint_as_float(~e);
}
__device__ __forceinline__ void split_bf(float v, __nv_bfloat16& h, __nv_bfloat16& l) {
    h = __float2bfloat16(v);
    l = __float2bfloat16(v - __bfloat162float(h));
}
__device__ __forceinline__ uint32_t smem_u32(const void* p) {
    uint32_t a;
    asm("{ .reg .u64 t; cvta.to.shared.u64 t, %1; cvt.u32.u64 %0, t; }" : "=r"(a) : "l"(p));
    return a;
}
#define LDSM4(r0, r1, r2, r3, addr) \
    asm volatile("ldmatrix.sync.aligned.m8n8.x4.shared.b16 {%0,%1,%2,%3}, [%4];" \
        : "=r"(r0), "=r"(r1), "=r"(r2), "=r"(r3) : "r"(addr))
__device__ __forceinline__ void mma16(float* c, const uint32_t* a, const uint32_t* b) {
    asm volatile("mma.sync.aligned.m16n8k16.row.col.f32.bf16.bf16.f32 "
        "{%0,%1,%2,%3}, {%4,%5,%6,%7}, {%8,%9}, {%0,%1,%2,%3};"
        : "+f"(c[0]), "+f"(c[1]), "+f"(c[2]), "+f"(c[3])
        : "r"(a[0]), "r"(a[1]), "r"(a[2]), "r"(a[3]), "r"(b[0]), "r"(b[1]));
}
#define CP16(dst, src, sz) \
    asm volatile("cp.async.cg.shared.global [%0], [%1], 16, %2;" \
        :: "r"(dst), "l"(src), "r"(sz) : "memory")
#define CP_COMMIT() asm volatile("cp.async.commit_group;" ::: "memory")
#define CP_WAIT0()  asm volatile("cp.async.wait_group 0;" ::: "memory")
#define CP_WAIT1()  asm volatile("cp.async.wait_group 1;" ::: "memory")

// ---------------- graph preprocessing ----------------
__global__ void k_count(const int* __restrict__ ei, int E) {
    int e = blockIdx.x * blockDim.x + threadIdx.x;
    if (e < E) atomicAdd(&g_cnt[ei[E + e]], 1);
}
__global__ void k_scan_blk(int N) {
    __shared__ int sh[256];
    int i = blockIdx.x * 256 + threadIdx.x;
    int v = (i < N) ? g_cnt[i] : 0;
    sh[threadIdx.x] = v;
    __syncthreads();
    for (int o = 1; o < 256; o <<= 1) {
        int a = (threadIdx.x >= o) ? sh[threadIdx.x - o] : 0;
        __syncthreads();
        sh[threadIdx.x] += a;
        __syncthreads();
    }
    if (i < N) g_part[i] = sh[threadIdx.x] - v;
    if (threadIdx.x == 255) g_bsum[blockIdx.x] = sh[255];
}
// merged top-level scan + offsets + cursor + dis + self-clean g_cnt
__global__ void k_scan_add(int N, int SB) {
    __shared__ int sh[128];
    int t = threadIdx.x;
    if (t < 128) sh[t] = (t < SB) ? g_bsum[t] : 0;
    __syncthreads();
    for (int o = 1; o < 128; o <<= 1) {
        int a = (t >= o && t < 128) ? sh[t - o] : 0;
        __syncthreads();
        if (t < 128) sh[t] += a;
        __syncthreads();
    }
    int i = blockIdx.x * 256 + t;
    if (i >= N) return;
    int pre = sh[blockIdx.x] - g_bsum[blockIdx.x];   // exclusive block prefix
    int off = g_part[i] + pre;
    int c = g_cnt[i];
    g_cnt[i] = 0;                                    // self-clean for next call
    g_offs[i] = off;
    g_cursor[i] = off;
    if (i == N - 1) g_offs[N] = off + c;
    g_dis[i] = rsqrtf((float)c + 1.0f);              // +1 self-loop
}
__global__ void k_fill(const int* __restrict__ ei, int E) {
    int e = blockIdx.x * blockDim.x + threadIdx.x;
    if (e >= E) return;
    int s = ei[e], d = ei[E + e];
    int p = atomicAdd(&g_cursor[d], 1);
    g_csr[p] = make_int2(s, __float_as_int(g_dis[s]));
}

// aggregate raw x (9 ch) -> split bf16 A0 [N x 64]
__global__ void k_aggregate_x(const float* __restrict__ x, int N) {
    int warp = (blockIdx.x * blockDim.x + threadIdx.x) >> 5;
    int lane = threadIdx.x & 31;
    if (warp >= N) return;
    int n = warp;
    int s0 = g_offs[n], s1 = g_offs[n + 1];
    float acc[INCH];
#pragma unroll
    for (int c = 0; c < INCH; c++) acc[c] = 0.f;
    for (int e = s0 + lane; e < s1; e += 32) {
        int2 ed = g_csr[e];
        float w = __int_as_float(ed.y);
#pragma unroll
        for (int c = 0; c < INCH; c++) acc[c] += w * x[ed.x * INCH + c];
    }
#pragma unroll
    for (int c = 0; c < INCH; c++)
#pragma unroll
        for (int o = 16; o; o >>= 1)
            acc[c] += __shfl_xor_sync(0xffffffffu, acc[c], o);
    if (lane == 0) {
        float dn = g_dis[n];
#pragma unroll
        for (int c = 0; c < INCH; c++) {
            float v = dn * acc[c] + dn * dn * x[n * INCH + c];
            __nv_bfloat16 h, l; split_bf(v, h, l);
            g_A0h[n * 64 + c] = h;
            g_A0l[n * 64 + c] = l;
        }
    }
    for (int c = INCH + lane; c < 64; c += 32) {
        g_A0h[n * 64 + c] = __float2bfloat16(0.f);
        g_A0l[n * 64 + c] = __float2bfloat16(0.f);
    }
}

// weight transpose + split + pad, BN fold, pool init
// blocks: [0,48) W0 | [48,480) Wh | [480,1056) Wjk | [1056,1059) bn | [1059,1782) pool
__global__ void k_wprep(const float* __restrict__ W0, const float* __restrict__ Wh,
                        const float* __restrict__ Wjk,
                        const float* __restrict__ gamma, const float* __restrict__ beta,
                        const float* __restrict__ mean, const float* __restrict__ var,
                        int G) {
    int b = blockIdx.x, t = threadIdx.x;
    if (b < 48) {
        int idx = b * 256 + t;
        int n = idx >> 6, k = idx & 63;
        float v = (n < HID && k < INCH) ? W0[k * HID + n] : 0.f;
        __nv_bfloat16 h, l; split_bf(v, h, l);
        g_W0th[idx] = h; g_W0tl[idx] = l;
    } else if (b < 480) {
        int q = b - 48;
        int L = q / 144;
        int idx = (q - L * 144) * 256 + t;
        int n = idx / 192, k = idx % 192;
        float v = (n < HID && k < HID) ? Wh[(size_t)L * HID * HID + k * HID + n] : 0.f;
        __nv_bfloat16 h, l; split_bf(v, h, l);
        g_Whth[L * 36864 + idx] = h; g_Whtl[L * 36864 + idx] = l;
    } else if (b < 1056) {
        int idx = (b - 480) * 256 + t;
        int n = idx / 768, k = idx % 768;
        int layer = k / 192, c = k % 192;
        float v = (n < HID && c < HID) ? Wjk[(size_t)(layer * HID + c) * HID + n] : 0.f;
        __nv_bfloat16 h, l; split_bf(v, h, l);
        g_Wjkth[idx] = h; g_Wjktl[idx] = l;
    } else if (b < 1059) {
        int i = (b - 1056) * 256 + t;
        if (i < 4 * HID) {
            float sc = gamma[i] * rsqrtf(var[i] + 1e-5f);
            g_bnscale[i] = sc;
            g_bnshift[i] = beta[i] - mean[i] * sc;
        }
    } else {
        int i = (b - 1059) * 256 + t;
        if (i < G * HID) g_pool[i] = 0x007FFFFFu;    // enc(-inf)
    }
}

// ---------------- bf16x3 GEMM, cp.async double-buffered ----------------
#define STG 55296
#define SMEM_BYTES (2 * STG)

__device__ __forceinline__ void ld_stage(
    uint32_t smb,
    const __nv_bfloat16* __restrict__ Ah, const __nv_bfloat16* __restrict__ Al, int lda,
    const __nv_bfloat16* __restrict__ Bh, const __nv_bfloat16* __restrict__ Bl, int ldb,
    int rowBase, int colBase, int k0, int Nrows, int tid) {
#pragma unroll
    for (int s = 0; s < 4; s++) {
        int idx = tid + s * 256;
        int r = idx >> 3, j = idx & 7;
        int gr = rowBase + r;
        int sz = (gr < Nrows) ? 16 : 0;
        int grc = min(gr, Nrows - 1);
        size_t go = (size_t)grc * lda + k0 + j * 8;
        uint32_t d = smb + r * 144 + j * 16;
        CP16(d,         Ah + go, sz);
        CP16(d + 18432, Al + go, sz);
    }
#pragma unroll
    for (int s = 0; s < 2; s++) {
        int idx = tid + s * 256;
        int n = idx >> 3, j = idx & 7;
        size_t go = (size_t)(colBase + n) * ldb + k0 + j * 8;
        uint32_t d = smb + 36864 + n * 144 + j * 16;
        CP16(d,        Bh + go, 16);
        CP16(d + 9216, Bl + go, 16);
    }
}

// mode 0: fp32 -> Cf (stride LDT, float2)  mode 2: bias+bn+relu -> split bf16x2
// mode 3: bias -> atomicMax pool
__global__ void __launch_bounds__(256)
k_mma(const __nv_bfloat16* __restrict__ Ah, const __nv_bfloat16* __restrict__ Al, int lda,
      const __nv_bfloat16* __restrict__ Bh, const __nv_bfloat16* __restrict__ Bl, int ldb,
      int Nrows, int Ktiles,
      float* __restrict__ Cf,
      __nv_bfloat16* __restrict__ Oh, __nv_bfloat16* __restrict__ Ol,
      const float* __restrict__ bias, const float* __restrict__ scale,
      const float* __restrict__ shift,
      const int* __restrict__ batch, unsigned* __restrict__ pool, int mode) {
    extern __shared__ __align__(16) char smch[];
    uint32_t sb = smem_u32(smch);

    int tid = threadIdx.x, lane = tid & 31, w = tid >> 5;
    int wm = w & 3, wn = w >> 2;
    int rowBase = blockIdx.y * 128, colBase = blockIdx.x * 64;

    float acc[2][4][4];
#pragma unroll
    for (int i = 0; i < 2; i++)
#pragma unroll
        for (int j = 0; j < 4; j++)
#pragma unroll
            for (int q = 0; q < 4; q++) acc[i][j][q] = 0.f;

    const uint32_t offA = (uint32_t)((wm * 32 + (lane & 15)) * 72 + (lane >> 4) * 8) << 1;
    const uint32_t offB = 36864u +
        ((uint32_t)((wn * 32 + (lane & 7) + ((lane >> 4) << 3)) * 72 + ((lane >> 3) & 1) * 8) << 1);
    const uint32_t A_LO = 18432, B_LO = 9216, MF = 2304;

    ld_stage(sb, Ah, Al, lda, Bh, Bl, ldb, rowBase, colBase, 0, Nrows, tid);
    CP_COMMIT();

    for (int kt = 0; kt < Ktiles; kt++) {
        uint32_t stb = sb + (uint32_t)(kt & 1) * STG;
        if (kt + 1 < Ktiles) {
            ld_stage(sb + (uint32_t)((kt + 1) & 1) * STG, Ah, Al, lda, Bh, Bl, ldb,
                     rowBase, colBase, (kt + 1) * 64, Nrows, tid);
            CP_COMMIT();
            CP_WAIT1();
        } else {
            CP_WAIT0();
        }
        __syncthreads();

        uint32_t aA = stb + offA;
        uint32_t aB = stb + offB;
#pragma unroll
        for (int ks = 0; ks < 4; ks++) {
            uint32_t kso = ks * 32;
            uint32_t bh[4][2], bl[4][2];
            LDSM4(bh[0][0], bh[0][1], bh[1][0], bh[1][1], aB + kso);
            LDSM4(bh[2][0], bh[2][1], bh[3][0], bh[3][1], aB + MF + kso);
            LDSM4(bl[0][0], bl[0][1], bl[1][0], bl[1][1], aB + B_LO + kso);
            LDSM4(bl[2][0], bl[2][1], bl[3][0], bl[3][1], aB + B_LO + MF + kso);
#pragma unroll
            for (int mf = 0; mf < 2; mf++) {
                uint32_t ah[4], al[4];
                LDSM4(ah[0], ah[1], ah[2], ah[3], aA + mf * MF + kso);
                LDSM4(al[0], al[1], al[2], al[3], aA + A_LO + mf * MF + kso);
#pragma unroll
                for (int nf = 0; nf < 4; nf++) {
                    mma16(acc[mf][nf], ah, bh[nf]);
                    mma16(acc[mf][nf], ah, bl[nf]);
                    mma16(acc[mf][nf], al, bh[nf]);
                }
            }
        }
        __syncthreads();
    }

    // epilogue
    int gid = lane >> 2, tig = lane & 3;
#pragma unroll
    for (int mf = 0; mf < 2; mf++) {
#pragma unroll
        for (int half = 0; half < 2; half++) {
            int r = rowBase + wm * 32 + mf * 16 + gid + half * 8;
            if (r >= Nrows) continue;
            int bidx = (mode == 3) ? batch[r] : 0;
#pragma unroll
            for (int nf = 0; nf < 4; nf++) {
                int c0 = colBase + wn * 32 + nf * 8 + tig * 2;
                float v0 = acc[mf][nf][half * 2];
                float v1 = acc[mf][nf][half * 2 + 1];
                if (mode == 0) {
                    if (c0 < HID)
                        *(float2*)(Cf + (size_t)r * LDT + c0) = make_float2(v0, v1);
                } else if (mode == 2) {
                    float o0 = 0.f, o1 = 0.f;
                    if (c0 < HID)
                        o0 = fmaxf(fmaf(v0 + bias[c0], scale[c0], shift[c0]), 0.f);
                    if (c0 + 1 < HID)
                        o1 = fmaxf(fmaf(v1 + bias[c0 + 1], scale[c0 + 1], shift[c0 + 1]), 0.f);
                    __nv_bfloat16 h0, l0, h1, l1;
                    split_bf(o0, h0, l0);
                    split_bf(o1, h1, l1);
                    size_t di = (size_t)r * LDAH + c0;
                    *(__nv_bfloat162*)(Oh + di) = __nv_bfloat162(h0, h1);
                    *(__nv_bfloat162*)(Ol + di) = __nv_bfloat162(l0, l1);
                } else {
                    if (c0 < HID)
                        atomicMax(&pool[bidx * HID + c0], enc_f(v0 + bias[c0]));
                    if (c0 + 1 < HID)
                        atomicMax(&pool[bidx * HID + c0 + 1], enc_f(v1 + bias[c0 + 1]));
                }
            }
        }
    }
}

// aggregation: packed-CSR gather (float2), bias+bn+relu, split-write into concat
__global__ void k_aggregate_h(const float* __restrict__ tmp,
                              const float* __restrict__ bias,
                              const float* __restrict__ scale,
                              const float* __restrict__ shift,
                              int colofs, int N) {
    int n = blockIdx.x;
    int c0 = threadIdx.x * 2;   // 0..190
    float v0 = 0.f, v1 = 0.f;
    if (c0 < HID) {
        int s0 = g_offs[n], s1 = g_offs[n + 1];
        float a0 = 0.f, a1 = 0.f;
        int e = s0;
        for (; e + 4 <= s1; e += 4) {
            int2 e0 = g_csr[e],     e1 = g_csr[e + 1];
            int2 e2 = g_csr[e + 2], e3 = g_csr[e + 3];
            float2 p0 = *(const float2*)(tmp + (size_t)e0.x * LDT + c0);
            float2 p1 = *(const float2*)(tmp + (size_t)e1.x * LDT + c0);
            float2 p2 = *(const float2*)(tmp + (size_t)e2.x * LDT + c0);
            float2 p3 = *(const float2*)(tmp + (size_t)e3.x * LDT + c0);
            float w0 = __int_as_float(e0.y), w1 = __int_as_float(e1.y);
            float w2 = __int_as_float(e2.y), w3 = __int_as_float(e3.y);
            a0 += w0 * p0.x + w1 * p1.x + w2 * p2.x + w3 * p3.x;
            a1 += w0 * p0.y + w1 * p1.y + w2 * p2.y + w3 * p3.y;
        }
        for (; e < s1; ++e) {
            int2 ed = g_csr[e];
            float w = __int_as_float(ed.y);
            float2 p = *(const float2*)(tmp + (size_t)ed.x * LDT + c0);
            a0 += w * p.x;
            a1 += w * p.y;
        }
        float dn = g_dis[n];
        float2 self = *(const float2*)(tmp + (size_t)n * LDT + c0);
        v0 = dn * a0 + dn * dn * self.x + bias[c0];
        v0 = fmaxf(fmaf(v0, scale[c0], shift[c0]), 0.f);
        if (c0 + 1 < HID) {
            v1 = dn * a1 + dn * dn * self.y + bias[c0 + 1];
            v1 = fmaxf(fmaf(v1, scale[c0 + 1], shift[c0 + 1]), 0.f);
        }
    }
    __nv_bfloat16 h0, l0, h1, l1;
    split_bf(v0, h0, l0);
    split_bf(v1, h1, l1);
    size_t di = (size_t)n * LDAH + colofs + c0;
    *(__nv_bfloat162*)(g_Ah + di) = __nv_bfloat162(h0, h1);
    *(__nv_bfloat162*)(g_Al + di) = __nv_bfloat162(l0, l1);
}

__global__ void k_finalize(const float* __restrict__ Wout,
                           const float* __restrict__ bout,
                           float* __restrict__ out, int G) {
    int g = blockIdx.x, t = threadIdx.x;
    __shared__ float red[256];
    float p = 0.f;
    for (int c = t; c < HID; c += 256)
        p += dec_f(g_pool[g * HID + c]) * Wout[c];
    red[t] = p;
    __syncthreads();
    for (int o = 128; o; o >>= 1) {
        if (t < o) red[t] += red[t + o];
        __syncthreads();
    }
    if (t == 0) out[g] = red[0] + bout[0];
}

// ---------------- host launcher ----------------
extern "C" void kernel_launch(void* const* d_in, const int* in_sizes, int n_in,
                              void* d_out, int out_size) {
    const float* x     = (const float*)d_in[0];
    const int*   ei    = (const int*)  d_in[1];
    const int*   batch = (const int*)  d_in[2];
    const float* W0    = (const float*)d_in[3];
    const float* b0    = (const float*)d_in[4];
    const float* W_h   = (const float*)d_in[5];
    const float* b_h   = (const float*)d_in[6];
    const float* bn_g  = (const float*)d_in[7];
    const float* bn_b  = (const float*)d_in[8];
    const float* bn_m  = (const float*)d_in[9];
    const float* bn_v  = (const float*)d_in[10];
    const float* W_jk  = (const float*)d_in[11];
    const float* b_jk  = (const float*)d_in[12];
    const float* W_out = (const float*)d_in[13];
    const float* b_out = (const float*)d_in[14];
    float* out = (float*)d_out;

    int N = in_sizes[0] / INCH;
    int E = in_sizes[1] / 2;
    int G = out_size;
    int SB = (N + 255) / 256;
    int poolBlks = (G * HID + 255) / 256;

    cudaFuncSetAttribute(k_mma, cudaFuncAttributeMaxDynamicSharedMemorySize, SMEM_BYTES);

    __nv_bfloat16 *a0h, *a0l, *ah, *al, *w0h, *w0l, *whh, *whl, *wjh, *wjl;
    cudaGetSymbolAddress((void**)&a0h, g_A0h);
    cudaGetSymbolAddress((void**)&a0l, g_A0l);
    cudaGetSymbolAddress((void**)&ah,  g_Ah);
    cudaGetSymbolAddress((void**)&al,  g_Al);
    cudaGetSymbolAddress((void**)&w0h, g_W0th);
    cudaGetSymbolAddress((void**)&w0l, g_W0tl);
    cudaGetSymbolAddress((void**)&whh, g_Whth);
    cudaGetSymbolAddress((void**)&whl, g_Whtl);
    cudaGetSymbolAddress((void**)&wjh, g_Wjkth);
    cudaGetSymbolAddress((void**)&wjl, g_Wjktl);
    float *tmp, *bns, *bnh;
    cudaGetSymbolAddress((void**)&tmp, g_tmp);
    cudaGetSymbolAddress((void**)&bns, g_bnscale);
    cudaGetSymbolAddress((void**)&bnh, g_bnshift);
    unsigned* pool;
    cudaGetSymbolAddress((void**)&pool, g_pool);

    k_count<<<(E + 255) / 256, 256>>>(ei, E);
    k_scan_blk<<<SB, 256>>>(N);
    k_scan_add<<<SB, 256>>>(N, SB);
    k_fill<<<(E + 255) / 256, 256>>>(ei, E);
    k_aggregate_x<<<(N * 32 + 255) / 256, 256>>>(x, N);
    k_wprep<<<1059 + poolBlks, 256>>>(W0, W_h, W_jk, bn_g, bn_b, bn_m, bn_v, G);

    dim3 grid(3, (N + 127) / 128);

    // layer 0: (Âx)@W0 -> bias+bn0+relu -> split into concat cols [0,192)
    k_mma<<<grid, 256, SMEM_BYTES>>>(a0h, a0l, 64, w0h, w0l, 64, N, 1,
                                     (float*)0, ah, al,
                                     b0, bns, bnh, (const int*)0, (unsigned*)0, 2);
    // hidden layers 1..3
    for (int i = 1; i <= 3; i++) {
        k_mma<<<grid, 256, SMEM_BYTES>>>(ah + (size_t)(i - 1) * 192,
                                         al + (size_t)(i - 1) * 192, LDAH,
                                         whh + (size_t)(i - 1) * 36864,
                                         whl + (size_t)(i - 1) * 36864, 192,
                                         N, 3, tmp,
                                         (__nv_bfloat16*)0, (__nv_bfloat16*)0,
                                         (const float*)0, (const float*)0, (const float*)0,
                                         (const int*)0, (unsigned*)0, 0);
        k_aggregate_h<<<N, 96>>>(tmp, b_h + (size_t)(i - 1) * HID,
                                 bns + i * HID, bnh + i * HID, i * 192, N);
    }
    // JK GEMM fused with max-pool
    k_mma<<<grid, 256, SMEM_BYTES>>>(ah, al, LDAH, wjh, wjl, 768, N, 12,
                                     (float*)0, (__nv_bfloat16*)0, (__nv_bfloat16*)0,
                                     b_jk, (const float*)0, (const float*)0,
                                     batch, pool, 3);

    k_finalize<<<G, 256>>>(W_out, b_out, out, G);
}

// round 7
// speedup vs baseline: 1.2279x; 1.2279x over previous
#include <cuda_runtime.h>
#include <cuda_fp16.h>
#include <cstdint>
#include <math.h>

#define NMAX   25000
#define EMAX   400000
#define GMAX   1000
#define HID    185
#define INCH   9
#define LDAH   768      // padded concat width (4*192)
#define LDT    186      // tmp row stride (even -> float2-aligned)

// ---------------- scratch ----------------
__device__ int      g_cnt[NMAX];          // BSS zero at load; self-cleaned each call
__device__ int      g_part[NMAX];
__device__ int      g_bsum[128];
__device__ int      g_offs[NMAX + 1];
__device__ int      g_cursor[NMAX];
__device__ float    g_dis[NMAX];
__device__ __align__(16) int2 g_csr[EMAX];   // (src, weight bits)
__device__ __align__(16) __half g_A0[NMAX * 64];        // layer0 A (fp16 single)
__device__ __align__(16) __half g_Axs[NMAX * LDAH];     // concat activations (fp16 single)
__device__ __align__(16) __half g_W0th[192 * 64];
__device__ __align__(16) __half g_W0tl[192 * 64];
__device__ __align__(16) __half g_Whth[3 * 192 * 192];
__device__ __align__(16) __half g_Whtl[3 * 192 * 192];
__device__ __align__(16) __half g_Wjkth[192 * 768];
__device__ __align__(16) __half g_Wjktl[192 * 768];
__device__ __align__(16) float g_tmp[NMAX * LDT];
__device__ unsigned g_pool[GMAX * HID];
__device__ float    g_bnscale[4 * HID];
__device__ float    g_bnshift[4 * HID];

// ---------------- helpers ----------------
__device__ __forceinline__ unsigned enc_f(float f) {
    unsigned u = __float_as_uint(f);
    return (u & 0x80000000u) ? ~u : (u | 0x80000000u);
}
__device__ __forceinline__ float dec_f(unsigned e) {
    return (e & 0x80000000u) ? __uint_as_float(e & 0x7FFFFFFFu) : __uint_as_float(~e);
}
__device__ __forceinline__ void split_h(float v, __half& h, __half& l) {
    h = __float2half_rn(v);
    l = __float2half_rn(v - __half2float(h));
}
__device__ __forceinline__ uint32_t smem_u32(const void* p) {
    uint32_t a;
    asm("{ .reg .u64 t; cvta.to.shared.u64 t, %1; cvt.u32.u64 %0, t; }" : "=r"(a) : "l"(p));
    return a;
}
#define LDSM4(r0, r1, r2, r3, addr) \
    asm volatile("ldmatrix.sync.aligned.m8n8.x4.shared.b16 {%0,%1,%2,%3}, [%4];" \
        : "=r"(r0), "=r"(r1), "=r"(r2), "=r"(r3) : "r"(addr))
__device__ __forceinline__ void mma16(float* c, const uint32_t* a, const uint32_t* b) {
    asm volatile("mma.sync.aligned.m16n8k16.row.col.f32.f16.f16.f32 "
        "{%0,%1,%2,%3}, {%4,%5,%6,%7}, {%8,%9}, {%0,%1,%2,%3};"
        : "+f"(c[0]), "+f"(c[1]), "+f"(c[2]), "+f"(c[3])
        : "r"(a[0]), "r"(a[1]), "r"(a[2]), "r"(a[3]), "r"(b[0]), "r"(b[1]));
}
#define CP16(dst, src, sz) \
    asm volatile("cp.async.cg.shared.global [%0], [%1], 16, %2;" \
        :: "r"(dst), "l"(src), "r"(sz) : "memory")
#define CP_COMMIT() asm volatile("cp.async.commit_group;" ::: "memory")
#define CP_WAIT0()  asm volatile("cp.async.wait_group 0;" ::: "memory")
#define CP_WAIT1()  asm volatile("cp.async.wait_group 1;" ::: "memory")

// ---------------- graph preprocessing ----------------
__global__ void k_count(const int* __restrict__ ei, int E) {
    int e = blockIdx.x * blockDim.x + threadIdx.x;
    if (e < E) atomicAdd(&g_cnt[ei[E + e]], 1);
}
__global__ void k_scan_blk(int N) {
    __shared__ int sh[256];
    int i = blockIdx.x * 256 + threadIdx.x;
    int v = (i < N) ? g_cnt[i] : 0;
    sh[threadIdx.x] = v;
    __syncthreads();
    for (int o = 1; o < 256; o <<= 1) {
        int a = (threadIdx.x >= o) ? sh[threadIdx.x - o] : 0;
        __syncthreads();
        sh[threadIdx.x] += a;
        __syncthreads();
    }
    if (i < N) g_part[i] = sh[threadIdx.x] - v;
    if (threadIdx.x == 255) g_bsum[blockIdx.x] = sh[255];
}
__global__ void k_scan_add(int N, int SB) {
    __shared__ int sh[128];
    int t = threadIdx.x;
    if (t < 128) sh[t] = (t < SB) ? g_bsum[t] : 0;
    __syncthreads();
    for (int o = 1; o < 128; o <<= 1) {
        int a = (t >= o && t < 128) ? sh[t - o] : 0;
        __syncthreads();
        if (t < 128) sh[t] += a;
        __syncthreads();
    }
    int i = blockIdx.x * 256 + t;
    if (i >= N) return;
    int pre = sh[blockIdx.x] - g_bsum[blockIdx.x];
    int off = g_part[i] + pre;
    int c = g_cnt[i];
    g_cnt[i] = 0;
    g_offs[i] = off;
    g_cursor[i] = off;
    if (i == N - 1) g_offs[N] = off + c;
    g_dis[i] = rsqrtf((float)c + 1.0f);
}
__global__ void k_fill(const int* __restrict__ ei, int E) {
    int e = blockIdx.x * blockDim.x + threadIdx.x;
    if (e >= E) return;
    int s = ei[e], d = ei[E + e];
    int p = atomicAdd(&g_cursor[d], 1);
    g_csr[p] = make_int2(s, __float_as_int(g_dis[s]));
}

// aggregate raw x (9 ch) -> fp16 A0 [N x 64]
__global__ void k_aggregate_x(const float* __restrict__ x, int N) {
    int warp = (blockIdx.x * blockDim.x + threadIdx.x) >> 5;
    int lane = threadIdx.x & 31;
    if (warp >= N) return;
    int n = warp;
    int s0 = g_offs[n], s1 = g_offs[n + 1];
    float acc[INCH];
#pragma unroll
    for (int c = 0; c < INCH; c++) acc[c] = 0.f;
    for (int e = s0 + lane; e < s1; e += 32) {
        int2 ed = g_csr[e];
        float w = __int_as_float(ed.y);
#pragma unroll
        for (int c = 0; c < INCH; c++) acc[c] += w * x[ed.x * INCH + c];
    }
#pragma unroll
    for (int c = 0; c < INCH; c++)
#pragma unroll
        for (int o = 16; o; o >>= 1)
            acc[c] += __shfl_xor_sync(0xffffffffu, acc[c], o);
    if (lane == 0) {
        float dn = g_dis[n];
#pragma unroll
        for (int c = 0; c < INCH; c++) {
            float v = dn * acc[c] + dn * dn * x[n * INCH + c];
            g_A0[n * 64 + c] = __float2half_rn(v);
        }
    }
    for (int c = INCH + lane; c < 64; c += 32)
        g_A0[n * 64 + c] = __float2half_rn(0.f);
}

// weight transpose + fp16 split + pad, BN fold, pool init
__global__ void k_wprep(const float* __restrict__ W0, const float* __restrict__ Wh,
                        const float* __restrict__ Wjk,
                        const float* __restrict__ gamma, const float* __restrict__ beta,
                        const float* __restrict__ mean, const float* __restrict__ var,
                        int G) {
    int b = blockIdx.x, t = threadIdx.x;
    if (b < 48) {
        int idx = b * 256 + t;
        int n = idx >> 6, k = idx & 63;
        float v = (n < HID && k < INCH) ? W0[k * HID + n] : 0.f;
        __half h, l; split_h(v, h, l);
        g_W0th[idx] = h; g_W0tl[idx] = l;
    } else if (b < 480) {
        int q = b - 48;
        int L = q / 144;
        int idx = (q - L * 144) * 256 + t;
        int n = idx / 192, k = idx % 192;
        float v = (n < HID && k < HID) ? Wh[(size_t)L * HID * HID + k * HID + n] : 0.f;
        __half h, l; split_h(v, h, l);
        g_Whth[L * 36864 + idx] = h; g_Whtl[L * 36864 + idx] = l;
    } else if (b < 1056) {
        int idx = (b - 480) * 256 + t;
        int n = idx / 768, k = idx % 768;
        int layer = k / 192, c = k % 192;
        float v = (n < HID && c < HID) ? Wjk[(size_t)(layer * HID + c) * HID + n] : 0.f;
        __half h, l; split_h(v, h, l);
        g_Wjkth[idx] = h; g_Wjktl[idx] = l;
    } else if (b < 1059) {
        int i = (b - 1056) * 256 + t;
        if (i < 4 * HID) {
            float sc = gamma[i] * rsqrtf(var[i] + 1e-5f);
            g_bnscale[i] = sc;
            g_bnshift[i] = beta[i] - mean[i] * sc;
        }
    } else {
        int i = (b - 1059) * 256 + t;
        if (i < G * HID) g_pool[i] = 0x007FFFFFu;    // enc(-inf)
    }
}

// ---------------- fp16x2 GEMM, cp.async double-buffered ----------------
// stage layout (bytes): sA 0 (128x72h = 18432), sBh 18432 (64x72h = 9216), sBl 27648
#define STG 36864
#define SMEM_BYTES (2 * STG)

__device__ __forceinline__ void ld_stage(
    uint32_t smb,
    const __half* __restrict__ A, int lda,
    const __half* __restrict__ Bh, const __half* __restrict__ Bl, int ldb,
    int rowBase, int colBase, int k0, int Nrows, int tid) {
    // A: 128 rows x 64 halves = 1024 16B-chunks -> 4 iters
#pragma unroll
    for (int s = 0; s < 4; s++) {
        int idx = tid + s * 256;
        int r = idx >> 3, j = idx & 7;
        int gr = rowBase + r;
        int sz = (gr < Nrows) ? 16 : 0;
        int grc = min(gr, Nrows - 1);
        size_t go = (size_t)grc * lda + k0 + j * 8;
        CP16(smb + r * 144 + j * 16, A + go, sz);
    }
    // B: 64 rows x 64 halves, hi+lo -> 2 iters x 2
#pragma unroll
    for (int s = 0; s < 2; s++) {
        int idx = tid + s * 256;
        int n = idx >> 3, j = idx & 7;
        size_t go = (size_t)(colBase + n) * ldb + k0 + j * 8;
        uint32_t d = smb + 18432 + n * 144 + j * 16;
        CP16(d,        Bh + go, 16);
        CP16(d + 9216, Bl + go, 16);
    }
}

// mode 0: fp32 -> Cf (stride LDT, float2)  mode 2: bias+bn+relu -> fp16 half2
// mode 3: bias -> atomicMax pool
__global__ void __launch_bounds__(256)
k_mma(const __half* __restrict__ A, int lda,
      const __half* __restrict__ Bh, const __half* __restrict__ Bl, int ldb,
      int Nrows, int Ktiles,
      float* __restrict__ Cf,
      __half* __restrict__ O,
      const float* __restrict__ bias, const float* __restrict__ scale,
      const float* __restrict__ shift,
      const int* __restrict__ batch, unsigned* __restrict__ pool, int mode) {
    extern __shared__ __align__(16) char smch[];
    uint32_t sb = smem_u32(smch);

    int tid = threadIdx.x, lane = tid & 31, w = tid >> 5;
    int wm = w & 3, wn = w >> 2;
    int rowBase = blockIdx.y * 128, colBase = blockIdx.x * 64;

    float acc[2][4][4];
#pragma unroll
    for (int i = 0; i < 2; i++)
#pragma unroll
        for (int j = 0; j < 4; j++)
#pragma unroll
            for (int q = 0; q < 4; q++) acc[i][j][q] = 0.f;

    const uint32_t offA = (uint32_t)((wm * 32 + (lane & 15)) * 72 + (lane >> 4) * 8) << 1;
    const uint32_t offB = 18432u +
        ((uint32_t)((wn * 32 + (lane & 7) + ((lane >> 4) << 3)) * 72 + ((lane >> 3) & 1) * 8) << 1);
    const uint32_t B_LO = 9216, MF = 2304;

    ld_stage(sb, A, lda, Bh, Bl, ldb, rowBase, colBase, 0, Nrows, tid);
    CP_COMMIT();

    for (int kt = 0; kt < Ktiles; kt++) {
        uint32_t stb = sb + (uint32_t)(kt & 1) * STG;
        if (kt + 1 < Ktiles) {
            ld_stage(sb + (uint32_t)((kt + 1) & 1) * STG, A, lda, Bh, Bl, ldb,
                     rowBase, colBase, (kt + 1) * 64, Nrows, tid);
            CP_COMMIT();
            CP_WAIT1();
        } else {
            CP_WAIT0();
        }
        __syncthreads();

        uint32_t aA = stb + offA;
        uint32_t aB = stb + offB;
#pragma unroll
        for (int ks = 0; ks < 4; ks++) {
            uint32_t kso = ks * 32;
            uint32_t bh[4][2], bl[4][2];
            LDSM4(bh[0][0], bh[0][1], bh[1][0], bh[1][1], aB + kso);
            LDSM4(bh[2][0], bh[2][1], bh[3][0], bh[3][1], aB + MF + kso);
            LDSM4(bl[0][0], bl[0][1], bl[1][0], bl[1][1], aB + B_LO + kso);
            LDSM4(bl[2][0], bl[2][1], bl[3][0], bl[3][1], aB + B_LO + MF + kso);
#pragma unroll
            for (int mf = 0; mf < 2; mf++) {
                uint32_t ar[4];
                LDSM4(ar[0], ar[1], ar[2], ar[3], aA + mf * MF + kso);
#pragma unroll
                for (int nf = 0; nf < 4; nf++) {
                    mma16(acc[mf][nf], ar, bh[nf]);
                    mma16(acc[mf][nf], ar, bl[nf]);
                }
            }
        }
        __syncthreads();
    }

    // epilogue
    int gid = lane >> 2, tig = lane & 3;
#pragma unroll
    for (int mf = 0; mf < 2; mf++) {
#pragma unroll
        for (int half = 0; half < 2; half++) {
            int r = rowBase + wm * 32 + mf * 16 + gid + half * 8;
            if (r >= Nrows) continue;
            int bidx = (mode == 3) ? batch[r] : 0;
#pragma unroll
            for (int nf = 0; nf < 4; nf++) {
                int c0 = colBase + wn * 32 + nf * 8 + tig * 2;
                float v0 = acc[mf][nf][half * 2];
                float v1 = acc[mf][nf][half * 2 + 1];
                if (mode == 0) {
                    if (c0 < HID)
                        *(float2*)(Cf + (size_t)r * LDT + c0) = make_float2(v0, v1);
                } else if (mode == 2) {
                    float o0 = 0.f, o1 = 0.f;
                    if (c0 < HID)
                        o0 = fmaxf(fmaf(v0 + bias[c0], scale[c0], shift[c0]), 0.f);
                    if (c0 + 1 < HID)
                        o1 = fmaxf(fmaf(v1 + bias[c0 + 1], scale[c0 + 1], shift[c0 + 1]), 0.f);
                    *(__half2*)(O + (size_t)r * LDAH + c0) =
                        __halves2half2(__float2half_rn(o0), __float2half_rn(o1));
                } else {
                    if (c0 < HID)
                        atomicMax(&pool[bidx * HID + c0], enc_f(v0 + bias[c0]));
                    if (c0 + 1 < HID)
                        atomicMax(&pool[bidx * HID + c0 + 1], enc_f(v1 + bias[c0 + 1]));
                }
            }
        }
    }
}

// aggregation: packed-CSR gather (float2), bias+bn+relu, fp16 write into concat
__global__ void k_aggregate_h(const float* __restrict__ tmp,
                              const float* __restrict__ bias,
                              const float* __restrict__ scale,
                              const float* __restrict__ shift,
                              int colofs, int N) {
    int n = blockIdx.x;
    int c0 = threadIdx.x * 2;   // 0..190
    float v0 = 0.f, v1 = 0.f;
    if (c0 < HID) {
        int s0 = g_offs[n], s1 = g_offs[n + 1];
        float a0 = 0.f, a1 = 0.f;
        int e = s0;
        for (; e + 4 <= s1; e += 4) {
            int2 e0 = g_csr[e],     e1 = g_csr[e + 1];
            int2 e2 = g_csr[e + 2], e3 = g_csr[e + 3];
            float2 p0 = *(const float2*)(tmp + (size_t)e0.x * LDT + c0);
            float2 p1 = *(const float2*)(tmp + (size_t)e1.x * LDT + c0);
            float2 p2 = *(const float2*)(tmp + (size_t)e2.x * LDT + c0);
            float2 p3 = *(const float2*)(tmp + (size_t)e3.x * LDT + c0);
            float w0 = __int_as_float(e0.y), w1 = __int_as_float(e1.y);
            float w2 = __int_as_float(e2.y), w3 = __int_as_float(e3.y);
            a0 += w0 * p0.x + w1 * p1.x + w2 * p2.x + w3 * p3.x;
            a1 += w0 * p0.y + w1 * p1.y + w2 * p2.y + w3 * p3.y;
        }
        for (; e < s1; ++e) {
            int2 ed = g_csr[e];
            float w = __int_as_float(ed.y);
            float2 p = *(const float2*)(tmp + (size_t)ed.x * LDT + c0);
            a0 += w * p.x;
            a1 += w * p.y;
        }
        float dn = g_dis[n];
        float2 self = *(const float2*)(tmp + (size_t)n * LDT + c0);
        v0 = dn * a0 + dn * dn * self.x + bias[c0];
        v0 = fmaxf(fmaf(v0, scale[c0], shift[c0]), 0.f);
        if (c0 + 1 < HID) {
            v1 = dn * a1 + dn * dn * self.y + bias[c0 + 1];
            v1 = fmaxf(fmaf(v1, scale[c0 + 1], shift[c0 + 1]), 0.f);
        }
    }
    *(__half2*)(g_Axs + (size_t)n * LDAH + colofs + c0) =
        __halves2half2(__float2half_rn(v0), __float2half_rn(v1));
}

__global__ void k_finalize(const float* __restrict__ Wout,
                           const float* __restrict__ bout,
                           float* __restrict__ out, int G) {
    int g = blockIdx.x, t = threadIdx.x;
    __shared__ float red[256];
    float p = 0.f;
    for (int c = t; c < HID; c += 256)
        p += dec_f(g_pool[g * HID + c]) * Wout[c];
    red[t] = p;
    __syncthreads();
    for (int o = 128; o; o >>= 1) {
        if (t < o) red[t] += red[t + o];
        __syncthreads();
    }
    if (t == 0) out[g] = red[0] + bout[0];
}

// ---------------- host launcher ----------------
extern "C" void kernel_launch(void* const* d_in, const int* in_sizes, int n_in,
                              void* d_out, int out_size) {
    const float* x     = (const float*)d_in[0];
    const int*   ei    = (const int*)  d_in[1];
    const int*   batch = (const int*)  d_in[2];
    const float* W0    = (const float*)d_in[3];
    const float* b0    = (const float*)d_in[4];
    const float* W_h   = (const float*)d_in[5];
    const float* b_h   = (const float*)d_in[6];
    const float* bn_g  = (const float*)d_in[7];
    const float* bn_b  = (const float*)d_in[8];
    const float* bn_m  = (const float*)d_in[9];
    const float* bn_v  = (const float*)d_in[10];
    const float* W_jk  = (const float*)d_in[11];
    const float* b_jk  = (const float*)d_in[12];
    const float* W_out = (const float*)d_in[13];
    const float* b_out = (const float*)d_in[14];
    float* out = (float*)d_out;

    int N = in_sizes[0] / INCH;
    int E = in_sizes[1] / 2;
    int G = out_size;
    int SB = (N + 255) / 256;
    int poolBlks = (G * HID + 255) / 256;

    cudaFuncSetAttribute(k_mma, cudaFuncAttributeMaxDynamicSharedMemorySize, SMEM_BYTES);

    __half *a0, *axs, *w0h, *w0l, *whh, *whl, *wjh, *wjl;
    cudaGetSymbolAddress((void**)&a0,  g_A0);
    cudaGetSymbolAddress((void**)&axs, g_Axs);
    cudaGetSymbolAddress((void**)&w0h, g_W0th);
    cudaGetSymbolAddress((void**)&w0l, g_W0tl);
    cudaGetSymbolAddress((void**)&whh, g_Whth);
    cudaGetSymbolAddress((void**)&whl, g_Whtl);
    cudaGetSymbolAddress((void**)&wjh, g_Wjkth);
    cudaGetSymbolAddress((void**)&wjl, g_Wjktl);
    float *tmp, *bns, *bnh;
    cudaGetSymbolAddress((void**)&tmp, g_tmp);
    cudaGetSymbolAddress((void**)&bns, g_bnscale);
    cudaGetSymbolAddress((void**)&bnh, g_bnshift);
    unsigned* pool;
    cudaGetSymbolAddress((void**)&pool, g_pool);

    k_count<<<(E + 255) / 256, 256>>>(ei, E);
    k_scan_blk<<<SB, 256>>>(N);
    k_scan_add<<<SB, 256>>>(N, SB);
    k_fill<<<(E + 255) / 256, 256>>>(ei, E);
    k_aggregate_x<<<(N * 32 + 255) / 256, 256>>>(x, N);
    k_wprep<<<1059 + poolBlks, 256>>>(W0, W_h, W_jk, bn_g, bn_b, bn_m, bn_v, G);

    dim3 grid(3, (N + 127) / 128);

    // layer 0: (Âx)@W0 -> bias+bn0+relu -> fp16 concat cols [0,192)
    k_mma<<<grid, 256, SMEM_BYTES>>>(a0, 64, w0h, w0l, 64, N, 1,
                                     (float*)0, axs,
                                     b0, bns, bnh, (const int*)0, (unsigned*)0, 2);
    // hidden layers 1..3
    for (int i = 1; i <= 3; i++) {
        k_mma<<<grid, 256, SMEM_BYTES>>>(axs + (size_t)(i - 1) * 192, LDAH,
                                         whh + (size_t)(i - 1) * 36864,
                                         whl + (size_t)(i - 1) * 36864, 192,
                                         N, 3, tmp, (__half*)0,
                                         (const float*)0, (const float*)0, (const float*)0,
                                         (const int*)0, (unsigned*)0, 0);
        k_aggregate_h<<<N, 96>>>(tmp, b_h + (size_t)(i - 1) * HID,
                                 bns + i * HID, bnh + i * HID, i * 192, N);
    }
    // JK GEMM fused with max-pool
    k_mma<<<grid, 256, SMEM_BYTES>>>(axs, LDAH, wjh, wjl, 768, N, 12,
                                     (float*)0, (__half*)0,
                                     b_jk, (const float*)0, (const float*)0,
                                     batch, pool, 3);

    k_finalize<<<G, 256>>>(W_out, b_out, out, G);
}

// round 8
// speedup vs baseline: 1.3238x; 1.0781x over previous
#include <cuda_runtime.h>
#include <cuda_fp16.h>
#include <cstdint>
#include <math.h>

#define NMAX   25000
#define EMAX   400000
#define GMAX   1000
#define HID    185
#define INCH   9
#define LDAH   768      // padded concat width (4*192)
#define LDZ    192      // aggregated-activation row stride

// ---------------- scratch ----------------
__device__ int      g_cnt[NMAX];          // BSS zero; self-cleaned each call
__device__ int      g_part[NMAX];
__device__ int      g_bsum[128];
__device__ int      g_offs[NMAX + 1];
__device__ int      g_cursor[NMAX];
__device__ float    g_dis[NMAX];
__device__ __align__(16) int2 g_csr[EMAX];   // (src, weight bits)
__device__ __align__(16) __half g_A0[NMAX * 64];        // layer0 aggregated input (fp16)
__device__ __align__(16) __half g_Axs[NMAX * LDAH];     // concat activations (fp16)
__device__ __align__(16) __half g_Z[NMAX * LDZ];        // aggregated activations (fp16)
__device__ __align__(16) __half g_W0th[192 * 64];
__device__ __align__(16) __half g_W0tl[192 * 64];
__device__ __align__(16) __half g_Whth[3 * 192 * 192];
__device__ __align__(16) __half g_Whtl[3 * 192 * 192];
__device__ __align__(16) __half g_Wjkth[192 * 768];
__device__ __align__(16) __half g_Wjktl[192 * 768];
__device__ unsigned g_pool[GMAX * HID];
__device__ float    g_bnscale[4 * HID];
__device__ float    g_bnshift[4 * HID];

// ---------------- helpers ----------------
__device__ __forceinline__ unsigned enc_f(float f) {
    unsigned u = __float_as_uint(f);
    return (u & 0x80000000u) ? ~u : (u | 0x80000000u);
}
__device__ __forceinline__ float dec_f(unsigned e) {
    return (e & 0x80000000u) ? __uint_as_float(e & 0x7FFFFFFFu) : __uint_as_float(~e);
}
__device__ __forceinline__ void split_h(float v, __half& h, __half& l) {
    h = __float2half_rn(v);
    l = __float2half_rn(v - __half2float(h));
}
__device__ __forceinline__ uint32_t smem_u32(const void* p) {
    uint32_t a;
    asm("{ .reg .u64 t; cvta.to.shared.u64 t, %1; cvt.u32.u64 %0, t; }" : "=r"(a) : "l"(p));
    return a;
}
#define LDSM4(r0, r1, r2, r3, addr) \
    asm volatile("ldmatrix.sync.aligned.m8n8.x4.shared.b16 {%0,%1,%2,%3}, [%4];" \
        : "=r"(r0), "=r"(r1), "=r"(r2), "=r"(r3) : "r"(addr))
__device__ __forceinline__ void mma16(float* c, const uint32_t* a, const uint32_t* b) {
    asm volatile("mma.sync.aligned.m16n8k16.row.col.f32.f16.f16.f32 "
        "{%0,%1,%2,%3}, {%4,%5,%6,%7}, {%8,%9}, {%0,%1,%2,%3};"
        : "+f"(c[0]), "+f"(c[1]), "+f"(c[2]), "+f"(c[3])
        : "r"(a[0]), "r"(a[1]), "r"(a[2]), "r"(a[3]), "r"(b[0]), "r"(b[1]));
}
#define CP16(dst, src, sz) \
    asm volatile("cp.async.cg.shared.global [%0], [%1], 16, %2;" \
        :: "r"(dst), "l"(src), "r"(sz) : "memory")
#define CP_COMMIT() asm volatile("cp.async.commit_group;" ::: "memory")
#define CP_WAIT0()  asm volatile("cp.async.wait_group 0;" ::: "memory")
#define CP_WAIT1()  asm volatile("cp.async.wait_group 1;" ::: "memory")

// ---------------- graph preprocessing ----------------
__global__ void k_count(const int* __restrict__ ei, int E) {
    int e = blockIdx.x * blockDim.x + threadIdx.x;
    if (e < E) atomicAdd(&g_cnt[ei[E + e]], 1);
}
__global__ void k_scan_blk(int N) {
    __shared__ int sh[256];
    int i = blockIdx.x * 256 + threadIdx.x;
    int v = (i < N) ? g_cnt[i] : 0;
    sh[threadIdx.x] = v;
    __syncthreads();
    for (int o = 1; o < 256; o <<= 1) {
        int a = (threadIdx.x >= o) ? sh[threadIdx.x - o] : 0;
        __syncthreads();
        sh[threadIdx.x] += a;
        __syncthreads();
    }
    if (i < N) g_part[i] = sh[threadIdx.x] - v;
    if (threadIdx.x == 255) g_bsum[blockIdx.x] = sh[255];
}
__global__ void k_scan_add(int N, int SB) {
    __shared__ int sh[128];
    int t = threadIdx.x;
    if (t < 128) sh[t] = (t < SB) ? g_bsum[t] : 0;
    __syncthreads();
    for (int o = 1; o < 128; o <<= 1) {
        int a = (t >= o && t < 128) ? sh[t - o] : 0;
        __syncthreads();
        if (t < 128) sh[t] += a;
        __syncthreads();
    }
    int i = blockIdx.x * 256 + t;
    if (i >= N) return;
    int pre = sh[blockIdx.x] - g_bsum[blockIdx.x];
    int off = g_part[i] + pre;
    int c = g_cnt[i];
    g_cnt[i] = 0;
    g_offs[i] = off;
    g_cursor[i] = off;
    if (i == N - 1) g_offs[N] = off + c;
    g_dis[i] = rsqrtf((float)c + 1.0f);
}
__global__ void k_fill(const int* __restrict__ ei, int E) {
    int e = blockIdx.x * blockDim.x + threadIdx.x;
    if (e >= E) return;
    int s = ei[e], d = ei[E + e];
    int p = atomicAdd(&g_cursor[d], 1);
    g_csr[p] = make_int2(s, __float_as_int(g_dis[s]));
}

// aggregate raw x (9 ch) -> fp16 A0 [N x 64]
__global__ void k_aggregate_x(const float* __restrict__ x, int N) {
    int warp = (blockIdx.x * blockDim.x + threadIdx.x) >> 5;
    int lane = threadIdx.x & 31;
    if (warp >= N) return;
    int n = warp;
    int s0 = g_offs[n], s1 = g_offs[n + 1];
    float acc[INCH];
#pragma unroll
    for (int c = 0; c < INCH; c++) acc[c] = 0.f;
    for (int e = s0 + lane; e < s1; e += 32) {
        int2 ed = g_csr[e];
        float w = __int_as_float(ed.y);
#pragma unroll
        for (int c = 0; c < INCH; c++) acc[c] += w * x[ed.x * INCH + c];
    }
#pragma unroll
    for (int c = 0; c < INCH; c++)
#pragma unroll
        for (int o = 16; o; o >>= 1)
            acc[c] += __shfl_xor_sync(0xffffffffu, acc[c], o);
    if (lane == 0) {
        float dn = g_dis[n];
#pragma unroll
        for (int c = 0; c < INCH; c++) {
            float v = dn * acc[c] + dn * dn * x[n * INCH + c];
            g_A0[n * 64 + c] = __float2half_rn(v);
        }
    }
    for (int c = INCH + lane; c < 64; c += 32)
        g_A0[n * 64 + c] = __float2half_rn(0.f);
}

// weight transpose + fp16 split + pad, BN fold, pool init
__global__ void k_wprep(const float* __restrict__ W0, const float* __restrict__ Wh,
                        const float* __restrict__ Wjk,
                        const float* __restrict__ gamma, const float* __restrict__ beta,
                        const float* __restrict__ mean, const float* __restrict__ var,
                        int G) {
    int b = blockIdx.x, t = threadIdx.x;
    if (b < 48) {
        int idx = b * 256 + t;
        int n = idx >> 6, k = idx & 63;
        float v = (n < HID && k < INCH) ? W0[k * HID + n] : 0.f;
        __half h, l; split_h(v, h, l);
        g_W0th[idx] = h; g_W0tl[idx] = l;
    } else if (b < 480) {
        int q = b - 48;
        int L = q / 144;
        int idx = (q - L * 144) * 256 + t;
        int n = idx / 192, k = idx % 192;
        float v = (n < HID && k < HID) ? Wh[(size_t)L * HID * HID + k * HID + n] : 0.f;
        __half h, l; split_h(v, h, l);
        g_Whth[L * 36864 + idx] = h; g_Whtl[L * 36864 + idx] = l;
    } else if (b < 1056) {
        int idx = (b - 480) * 256 + t;
        int n = idx / 768, k = idx % 768;
        int layer = k / 192, c = k % 192;
        float v = (n < HID && c < HID) ? Wjk[(size_t)(layer * HID + c) * HID + n] : 0.f;
        __half h, l; split_h(v, h, l);
        g_Wjkth[idx] = h; g_Wjktl[idx] = l;
    } else if (b < 1059) {
        int i = (b - 1056) * 256 + t;
        if (i < 4 * HID) {
            float sc = gamma[i] * rsqrtf(var[i] + 1e-5f);
            g_bnscale[i] = sc;
            g_bnshift[i] = beta[i] - mean[i] * sc;
        }
    } else {
        int i = (b - 1059) * 256 + t;
        if (i < G * HID) g_pool[i] = 0x007FFFFFu;    // enc(-inf)
    }
}

// ---------------- fp16x2 GEMM, cp.async double-buffered ----------------
// stage (bytes): sA 0 (128x72h = 18432), sBh 18432 (64x72h = 9216), sBl 27648
#define STG 36864
#define SMEM_BYTES (2 * STG)

__device__ __forceinline__ void ld_stage(
    uint32_t smb,
    const __half* __restrict__ A, int lda,
    const __half* __restrict__ Bh, const __half* __restrict__ Bl, int ldb,
    int rowBase, int colBase, int k0, int Nrows, int tid) {
#pragma unroll
    for (int s = 0; s < 4; s++) {
        int idx = tid + s * 256;
        int r = idx >> 3, j = idx & 7;
        int gr = rowBase + r;
        int sz = (gr < Nrows) ? 16 : 0;
        int grc = min(gr, Nrows - 1);
        size_t go = (size_t)grc * lda + k0 + j * 8;
        CP16(smb + r * 144 + j * 16, A + go, sz);
    }
#pragma unroll
    for (int s = 0; s < 2; s++) {
        int idx = tid + s * 256;
        int n = idx >> 3, j = idx & 7;
        size_t go = (size_t)(colBase + n) * ldb + k0 + j * 8;
        uint32_t d = smb + 18432 + n * 144 + j * 16;
        CP16(d,        Bh + go, 16);
        CP16(d + 9216, Bl + go, 16);
    }
}

// mode 2: bias+bn+relu -> fp16 half2 into O (cols >= HID zeroed)
// mode 3: bias -> atomicMax pool
__global__ void __launch_bounds__(256)
k_mma(const __half* __restrict__ A, int lda,
      const __half* __restrict__ Bh, const __half* __restrict__ Bl, int ldb,
      int Nrows, int Ktiles,
      __half* __restrict__ O,
      const float* __restrict__ bias, const float* __restrict__ scale,
      const float* __restrict__ shift,
      const int* __restrict__ batch, unsigned* __restrict__ pool, int mode) {
    extern __shared__ __align__(16) char smch[];
    uint32_t sb = smem_u32(smch);

    int tid = threadIdx.x, lane = tid & 31, w = tid >> 5;
    int wm = w & 3, wn = w >> 2;
    int rowBase = blockIdx.y * 128, colBase = blockIdx.x * 64;

    float acc[2][4][4];
#pragma unroll
    for (int i = 0; i < 2; i++)
#pragma unroll
        for (int j = 0; j < 4; j++)
#pragma unroll
            for (int q = 0; q < 4; q++) acc[i][j][q] = 0.f;

    const uint32_t offA = (uint32_t)((wm * 32 + (lane & 15)) * 72 + (lane >> 4) * 8) << 1;
    const uint32_t offB = 18432u +
        ((uint32_t)((wn * 32 + (lane & 7) + ((lane >> 4) << 3)) * 72 + ((lane >> 3) & 1) * 8) << 1);
    const uint32_t B_LO = 9216, MF = 2304;

    ld_stage(sb, A, lda, Bh, Bl, ldb, rowBase, colBase, 0, Nrows, tid);
    CP_COMMIT();

    for (int kt = 0; kt < Ktiles; kt++) {
        uint32_t stb = sb + (uint32_t)(kt & 1) * STG;
        if (kt + 1 < Ktiles) {
            ld_stage(sb + (uint32_t)((kt + 1) & 1) * STG, A, lda, Bh, Bl, ldb,
                     rowBase, colBase, (kt + 1) * 64, Nrows, tid);
            CP_COMMIT();
            CP_WAIT1();
        } else {
            CP_WAIT0();
        }
        __syncthreads();

        uint32_t aA = stb + offA;
        uint32_t aB = stb + offB;
#pragma unroll
        for (int ks = 0; ks < 4; ks++) {
            uint32_t kso = ks * 32;
            uint32_t bh[4][2], bl[4][2];
            LDSM4(bh[0][0], bh[0][1], bh[1][0], bh[1][1], aB + kso);
            LDSM4(bh[2][0], bh[2][1], bh[3][0], bh[3][1], aB + MF + kso);
            LDSM4(bl[0][0], bl[0][1], bl[1][0], bl[1][1], aB + B_LO + kso);
            LDSM4(bl[2][0], bl[2][1], bl[3][0], bl[3][1], aB + B_LO + MF + kso);
#pragma unroll
            for (int mf = 0; mf < 2; mf++) {
                uint32_t ar[4];
                LDSM4(ar[0], ar[1], ar[2], ar[3], aA + mf * MF + kso);
#pragma unroll
                for (int nf = 0; nf < 4; nf++) {
                    mma16(acc[mf][nf], ar, bh[nf]);
                    mma16(acc[mf][nf], ar, bl[nf]);
                }
            }
        }
        __syncthreads();
    }

    // epilogue
    int gid = lane >> 2, tig = lane & 3;
#pragma unroll
    for (int mf = 0; mf < 2; mf++) {
#pragma unroll
        for (int half = 0; half < 2; half++) {
            int r = rowBase + wm * 32 + mf * 16 + gid + half * 8;
            if (r >= Nrows) continue;
            int bidx = (mode == 3) ? batch[r] : 0;
#pragma unroll
            for (int nf = 0; nf < 4; nf++) {
                int c0 = colBase + wn * 32 + nf * 8 + tig * 2;
                float v0 = acc[mf][nf][half * 2];
                float v1 = acc[mf][nf][half * 2 + 1];
                if (mode == 2) {
                    float o0 = 0.f, o1 = 0.f;
                    if (c0 < HID)
                        o0 = fmaxf(fmaf(v0 + bias[c0], scale[c0], shift[c0]), 0.f);
                    if (c0 + 1 < HID)
                        o1 = fmaxf(fmaf(v1 + bias[c0 + 1], scale[c0 + 1], shift[c0 + 1]), 0.f);
                    *(__half2*)(O + (size_t)r * LDAH + c0) =
                        __halves2half2(__float2half_rn(o0), __float2half_rn(o1));
                } else {
                    if (c0 < HID)
                        atomicMax(&pool[bidx * HID + c0], enc_f(v0 + bias[c0]));
                    if (c0 + 1 < HID)
                        atomicMax(&pool[bidx * HID + c0 + 1], enc_f(v1 + bias[c0 + 1]));
                }
            }
        }
    }
}

// fp16 aggregation: z[n] = dn * sum_e w_e * h[src_e] + dn^2 * h[n]   (half2 lanes)
__global__ void k_agg16(const __half* __restrict__ src, int N) {
    int n = blockIdx.x;
    int c0 = threadIdx.x * 2;   // 0..190 (96 threads cover 192 cols)
    int s0 = g_offs[n], s1 = g_offs[n + 1];
    float a0 = 0.f, a1 = 0.f;
    int e = s0;
    for (; e + 4 <= s1; e += 4) {
        int2 e0 = g_csr[e],     e1 = g_csr[e + 1];
        int2 e2 = g_csr[e + 2], e3 = g_csr[e + 3];
        float2 p0 = __half22float2(*(const __half2*)(src + (size_t)e0.x * LDAH + c0));
        float2 p1 = __half22float2(*(const __half2*)(src + (size_t)e1.x * LDAH + c0));
        float2 p2 = __half22float2(*(const __half2*)(src + (size_t)e2.x * LDAH + c0));
        float2 p3 = __half22float2(*(const __half2*)(src + (size_t)e3.x * LDAH + c0));
        float w0 = __int_as_float(e0.y), w1 = __int_as_float(e1.y);
        float w2 = __int_as_float(e2.y), w3 = __int_as_float(e3.y);
        a0 += w0 * p0.x + w1 * p1.x + w2 * p2.x + w3 * p3.x;
        a1 += w0 * p0.y + w1 * p1.y + w2 * p2.y + w3 * p3.y;
    }
    for (; e < s1; ++e) {
        int2 ed = g_csr[e];
        float w = __int_as_float(ed.y);
        float2 p = __half22float2(*(const __half2*)(src + (size_t)ed.x * LDAH + c0));
        a0 += w * p.x;
        a1 += w * p.y;
    }
    float dn = g_dis[n];
    float2 self = __half22float2(*(const __half2*)(src + (size_t)n * LDAH + c0));
    float v0 = dn * a0 + dn * dn * self.x;
    float v1 = dn * a1 + dn * dn * self.y;
    *(__half2*)(g_Z + (size_t)n * LDZ + c0) = __floats2half2_rn(v0, v1);
}

__global__ void k_finalize(const float* __restrict__ Wout,
                           const float* __restrict__ bout,
                           float* __restrict__ out, int G) {
    int g = blockIdx.x, t = threadIdx.x;
    __shared__ float red[256];
    float p = 0.f;
    for (int c = t; c < HID; c += 256)
        p += dec_f(g_pool[g * HID + c]) * Wout[c];
    red[t] = p;
    __syncthreads();
    for (int o = 128; o; o >>= 1) {
        if (t < o) red[t] += red[t + o];
        __syncthreads();
    }
    if (t == 0) out[g] = red[0] + bout[0];
}

// ---------------- host launcher ----------------
extern "C" void kernel_launch(void* const* d_in, const int* in_sizes, int n_in,
                              void* d_out, int out_size) {
    const float* x     = (const float*)d_in[0];
    const int*   ei    = (const int*)  d_in[1];
    const int*   batch = (const int*)  d_in[2];
    const float* W0    = (const float*)d_in[3];
    const float* b0    = (const float*)d_in[4];
    const float* W_h   = (const float*)d_in[5];
    const float* b_h   = (const float*)d_in[6];
    const float* bn_g  = (const float*)d_in[7];
    const float* bn_b  = (const float*)d_in[8];
    const float* bn_m  = (const float*)d_in[9];
    const float* bn_v  = (const float*)d_in[10];
    const float* W_jk  = (const float*)d_in[11];
    const float* b_jk  = (const float*)d_in[12];
    const float* W_out = (const float*)d_in[13];
    const float* b_out = (const float*)d_in[14];
    float* out = (float*)d_out;

    int N = in_sizes[0] / INCH;
    int E = in_sizes[1] / 2;
    int G = out_size;
    int SB = (N + 255) / 256;
    int poolBlks = (G * HID + 255) / 256;

    cudaFuncSetAttribute(k_mma, cudaFuncAttributeMaxDynamicSharedMemorySize, SMEM_BYTES);

    __half *a0, *axs, *zz, *w0h, *w0l, *whh, *whl, *wjh, *wjl;
    cudaGetSymbolAddress((void**)&a0,  g_A0);
    cudaGetSymbolAddress((void**)&axs, g_Axs);
    cudaGetSymbolAddress((void**)&zz,  g_Z);
    cudaGetSymbolAddress((void**)&w0h, g_W0th);
    cudaGetSymbolAddress((void**)&w0l, g_W0tl);
    cudaGetSymbolAddress((void**)&whh, g_Whth);
    cudaGetSymbolAddress((void**)&whl, g_Whtl);
    cudaGetSymbolAddress((void**)&wjh, g_Wjkth);
    cudaGetSymbolAddress((void**)&wjl, g_Wjktl);
    float *bns, *bnh;
    cudaGetSymbolAddress((void**)&bns, g_bnscale);
    cudaGetSymbolAddress((void**)&bnh, g_bnshift);
    unsigned* pool;
    cudaGetSymbolAddress((void**)&pool, g_pool);

    k_count<<<(E + 255) / 256, 256>>>(ei, E);
    k_scan_blk<<<SB, 256>>>(N);
    k_scan_add<<<SB, 256>>>(N, SB);
    k_fill<<<(E + 255) / 256, 256>>>(ei, E);
    k_aggregate_x<<<(N * 32 + 255) / 256, 256>>>(x, N);
    k_wprep<<<1059 + poolBlks, 256>>>(W0, W_h, W_jk, bn_g, bn_b, bn_m, bn_v, G);

    dim3 grid(3, (N + 127) / 128);

    // layer 0: (Âx)@W0 -> bias+bn0+relu -> fp16 concat cols [0,192)
    k_mma<<<grid, 256, SMEM_BYTES>>>(a0, 64, w0h, w0l, 64, N, 1,
                                     axs, b0, bns, bnh,
                                     (const int*)0, (unsigned*)0, 2);
    // hidden layers 1..3: aggregate fp16 activations first, then GEMM+epilogue
    for (int i = 1; i <= 3; i++) {
        k_agg16<<<N, 96>>>(axs + (size_t)(i - 1) * 192, N);
        k_mma<<<grid, 256, SMEM_BYTES>>>(zz, LDZ,
                                         whh + (size_t)(i - 1) * 36864,
                                         whl + (size_t)(i - 1) * 36864, 192,
                                         N, 3,
                                         axs + (size_t)i * 192,
                                         b_h + (size_t)(i - 1) * HID,
                                         bns + i * HID, bnh + i * HID,
                                         (const int*)0, (unsigned*)0, 2);
    }
    // JK GEMM fused with max-pool
    k_mma<<<grid, 256, SMEM_BYTES>>>(axs, LDAH, wjh, wjl, 768, N, 12,
                                     (__half*)0,
                                     b_jk, (const float*)0, (const float*)0,
                                     batch, pool, 3);

    k_finalize<<<G, 256>>>(W_out, b_out, out, G);
}

// round 9
// speedup vs baseline: 1.3735x; 1.0375x over previous
#include <cuda_runtime.h>
#include <cuda_fp16.h>
#include <cstdint>
#include <math.h>

#define NMAX   25000
#define EMAX   400000
#define GMAX   1000
#define HID    185
#define INCH   9
#define LDAH   768      // padded concat width (4*192)
#define LDZ    192      // aggregated-activation row stride

// ---------------- scratch ----------------
__device__ int      g_cnt[NMAX];          // BSS zero; self-cleaned each call
__device__ int      g_part[NMAX];
__device__ int      g_bsum[128];
__device__ int      g_offs[NMAX + 1];
__device__ int      g_cursor[NMAX];
__device__ float    g_dis[NMAX];
__device__ __align__(16) int2 g_csr[EMAX];   // (src, weight bits)
__device__ __align__(16) __half g_A0[NMAX * 64];        // layer0 aggregated input (fp16)
__device__ __align__(16) __half g_Axs[NMAX * LDAH];     // concat activations (fp16)
__device__ __align__(16) __half g_Z[NMAX * LDZ];        // aggregated activations (fp16)
__device__ __align__(16) __half g_W0th[192 * 64];
__device__ __align__(16) __half g_W0tl[192 * 64];
__device__ __align__(16) __half g_Whth[3 * 192 * 192];
__device__ __align__(16) __half g_Whtl[3 * 192 * 192];
__device__ __align__(16) __half g_Wjkth[192 * 768];
__device__ unsigned g_pool[GMAX * HID];
__device__ float    g_bnscale[4 * HID];
__device__ float    g_bnshift[4 * HID];

// ---------------- helpers ----------------
__device__ __forceinline__ unsigned enc_f(float f) {
    unsigned u = __float_as_uint(f);
    return (u & 0x80000000u) ? ~u : (u | 0x80000000u);
}
__device__ __forceinline__ float dec_f(unsigned e) {
    return (e & 0x80000000u) ? __uint_as_float(e & 0x7FFFFFFFu) : __uint_as_float(~e);
}
__device__ __forceinline__ void split_h(float v, __half& h, __half& l) {
    h = __float2half_rn(v);
    l = __float2half_rn(v - __half2float(h));
}
__device__ __forceinline__ uint32_t smem_u32(const void* p) {
    uint32_t a;
    asm("{ .reg .u64 t; cvta.to.shared.u64 t, %1; cvt.u32.u64 %0, t; }" : "=r"(a) : "l"(p));
    return a;
}
#define LDSM4(r0, r1, r2, r3, addr) \
    asm volatile("ldmatrix.sync.aligned.m8n8.x4.shared.b16 {%0,%1,%2,%3}, [%4];" \
        : "=r"(r0), "=r"(r1), "=r"(r2), "=r"(r3) : "r"(addr))
__device__ __forceinline__ void mma16(float* c, const uint32_t* a, const uint32_t* b) {
    asm volatile("mma.sync.aligned.m16n8k16.row.col.f32.f16.f16.f32 "
        "{%0,%1,%2,%3}, {%4,%5,%6,%7}, {%8,%9}, {%0,%1,%2,%3};"
        : "+f"(c[0]), "+f"(c[1]), "+f"(c[2]), "+f"(c[3])
        : "r"(a[0]), "r"(a[1]), "r"(a[2]), "r"(a[3]), "r"(b[0]), "r"(b[1]));
}
#define CP16(dst, src, sz) \
    asm volatile("cp.async.cg.shared.global [%0], [%1], 16, %2;" \
        :: "r"(dst), "l"(src), "r"(sz) : "memory")
#define CP_COMMIT() asm volatile("cp.async.commit_group;" ::: "memory")
#define CP_WAIT0()  asm volatile("cp.async.wait_group 0;" ::: "memory")
#define CP_WAIT1()  asm volatile("cp.async.wait_group 1;" ::: "memory")

// ---------------- merged: edge count + weight prep + BN fold + pool init ----
// blocks: [0,EB) count | [EB,EB+48) W0 | [+48,+480) Wh | [+480,+1056) Wjk
//         [+1056,+1059) bn | [+1059, +1059+poolBlks) pool
__global__ void k_prep(const int* __restrict__ ei, int E, int EB,
                       const float* __restrict__ W0, const float* __restrict__ Wh,
                       const float* __restrict__ Wjk,
                       const float* __restrict__ gamma, const float* __restrict__ beta,
                       const float* __restrict__ mean, const float* __restrict__ var,
                       int G) {
    int t = threadIdx.x;
    if (blockIdx.x < EB) {
        int e = blockIdx.x * 256 + t;
        if (e < E) atomicAdd(&g_cnt[ei[E + e]], 1);
        return;
    }
    int b = blockIdx.x - EB;
    if (b < 48) {
        int idx = b * 256 + t;
        int n = idx >> 6, k = idx & 63;
        float v = (n < HID && k < INCH) ? W0[k * HID + n] : 0.f;
        __half h, l; split_h(v, h, l);
        g_W0th[idx] = h; g_W0tl[idx] = l;
    } else if (b < 480) {
        int q = b - 48;
        int L = q / 144;
        int idx = (q - L * 144) * 256 + t;
        int n = idx / 192, k = idx % 192;
        float v = (n < HID && k < HID) ? Wh[(size_t)L * HID * HID + k * HID + n] : 0.f;
        __half h, l; split_h(v, h, l);
        g_Whth[L * 36864 + idx] = h; g_Whtl[L * 36864 + idx] = l;
    } else if (b < 1056) {
        int idx = (b - 480) * 256 + t;
        int n = idx / 768, k = idx % 768;
        int layer = k / 192, c = k % 192;
        float v = (n < HID && c < HID) ? Wjk[(size_t)(layer * HID + c) * HID + n] : 0.f;
        g_Wjkth[idx] = __float2half_rn(v);
    } else if (b < 1059) {
        int i = (b - 1056) * 256 + t;
        if (i < 4 * HID) {
            float sc = gamma[i] * rsqrtf(var[i] + 1e-5f);
            g_bnscale[i] = sc;
            g_bnshift[i] = beta[i] - mean[i] * sc;
        }
    } else {
        int i = (b - 1059) * 256 + t;
        if (i < G * HID) g_pool[i] = 0x007FFFFFu;    // enc(-inf)
    }
}

__global__ void k_scan_blk(int N) {
    __shared__ int sh[256];
    int i = blockIdx.x * 256 + threadIdx.x;
    int v = (i < N) ? g_cnt[i] : 0;
    sh[threadIdx.x] = v;
    __syncthreads();
    for (int o = 1; o < 256; o <<= 1) {
        int a = (threadIdx.x >= o) ? sh[threadIdx.x - o] : 0;
        __syncthreads();
        sh[threadIdx.x] += a;
        __syncthreads();
    }
    if (i < N) g_part[i] = sh[threadIdx.x] - v;
    if (threadIdx.x == 255) g_bsum[blockIdx.x] = sh[255];
}
__global__ void k_scan_add(int N, int SB) {
    __shared__ int sh[128];
    int t = threadIdx.x;
    if (t < 128) sh[t] = (t < SB) ? g_bsum[t] : 0;
    __syncthreads();
    for (int o = 1; o < 128; o <<= 1) {
        int a = (t >= o && t < 128) ? sh[t - o] : 0;
        __syncthreads();
        if (t < 128) sh[t] += a;
        __syncthreads();
    }
    int i = blockIdx.x * 256 + t;
    if (i >= N) return;
    int pre = sh[blockIdx.x] - g_bsum[blockIdx.x];
    int off = g_part[i] + pre;
    int c = g_cnt[i];
    g_cnt[i] = 0;
    g_offs[i] = off;
    g_cursor[i] = off;
    if (i == N - 1) g_offs[N] = off + c;
    g_dis[i] = rsqrtf((float)c + 1.0f);
}
__global__ void k_fill(const int* __restrict__ ei, int E) {
    int e = blockIdx.x * blockDim.x + threadIdx.x;
    if (e >= E) return;
    int s = ei[e], d = ei[E + e];
    int p = atomicAdd(&g_cursor[d], 1);
    g_csr[p] = make_int2(s, __float_as_int(g_dis[s]));
}

// aggregate raw x (9 ch) -> fp16 A0 [N x 64]
__global__ void k_aggregate_x(const float* __restrict__ x, int N) {
    int warp = (blockIdx.x * blockDim.x + threadIdx.x) >> 5;
    int lane = threadIdx.x & 31;
    if (warp >= N) return;
    int n = warp;
    int s0 = g_offs[n], s1 = g_offs[n + 1];
    float acc[INCH];
#pragma unroll
    for (int c = 0; c < INCH; c++) acc[c] = 0.f;
    for (int e = s0 + lane; e < s1; e += 32) {
        int2 ed = g_csr[e];
        float w = __int_as_float(ed.y);
#pragma unroll
        for (int c = 0; c < INCH; c++) acc[c] += w * x[ed.x * INCH + c];
    }
#pragma unroll
    for (int c = 0; c < INCH; c++)
#pragma unroll
        for (int o = 16; o; o >>= 1)
            acc[c] += __shfl_xor_sync(0xffffffffu, acc[c], o);
    if (lane == 0) {
        float dn = g_dis[n];
#pragma unroll
        for (int c = 0; c < INCH; c++) {
            float v = dn * acc[c] + dn * dn * x[n * INCH + c];
            g_A0[n * 64 + c] = __float2half_rn(v);
        }
    }
    for (int c = INCH + lane; c < 64; c += 32)
        g_A0[n * 64 + c] = __float2half_rn(0.f);
}

// ---------------- fp16 GEMM (x2 or x1 weight split), cp.async double-buffered
// stage (bytes): sA 0 (128x72h = 18432), sBh 18432 (64x72h = 9216), sBl 27648
#define STG 36864
#define SMEM_BYTES (2 * STG)

__device__ __forceinline__ void ld_stage(
    uint32_t smb,
    const __half* __restrict__ A, int lda,
    const __half* __restrict__ Bh, const __half* __restrict__ Bl, int ldb,
    int rowBase, int colBase, int k0, int Nrows, int tid, int dual) {
#pragma unroll
    for (int s = 0; s < 4; s++) {
        int idx = tid + s * 256;
        int r = idx >> 3, j = idx & 7;
        int gr = rowBase + r;
        int sz = (gr < Nrows) ? 16 : 0;
        int grc = min(gr, Nrows - 1);
        size_t go = (size_t)grc * lda + k0 + j * 8;
        CP16(smb + r * 144 + j * 16, A + go, sz);
    }
#pragma unroll
    for (int s = 0; s < 2; s++) {
        int idx = tid + s * 256;
        int n = idx >> 3, j = idx & 7;
        size_t go = (size_t)(colBase + n) * ldb + k0 + j * 8;
        uint32_t d = smb + 18432 + n * 144 + j * 16;
        CP16(d, Bh + go, 16);
        if (dual) CP16(d + 9216, Bl + go, 16);
    }
}

// mode 2: bias+bn+relu -> fp16 half2 into O     mode 3: bias -> atomicMax pool
// dual: 1 = hi+lo weight split (2 MMAs/step), 0 = hi only
__global__ void __launch_bounds__(256)
k_mma(const __half* __restrict__ A, int lda,
      const __half* __restrict__ Bh, const __half* __restrict__ Bl, int ldb,
      int Nrows, int Ktiles,
      __half* __restrict__ O,
      const float* __restrict__ bias, const float* __restrict__ scale,
      const float* __restrict__ shift,
      const int* __restrict__ batch, unsigned* __restrict__ pool,
      int mode, int dual) {
    extern __shared__ __align__(16) char smch[];
    uint32_t sb = smem_u32(smch);

    int tid = threadIdx.x, lane = tid & 31, w = tid >> 5;
    int wm = w & 3, wn = w >> 2;
    int rowBase = blockIdx.y * 128, colBase = blockIdx.x * 64;

    float acc[2][4][4];
#pragma unroll
    for (int i = 0; i < 2; i++)
#pragma unroll
        for (int j = 0; j < 4; j++)
#pragma unroll
            for (int q = 0; q < 4; q++) acc[i][j][q] = 0.f;

    const uint32_t offA = (uint32_t)((wm * 32 + (lane & 15)) * 72 + (lane >> 4) * 8) << 1;
    const uint32_t offB = 18432u +
        ((uint32_t)((wn * 32 + (lane & 7) + ((lane >> 4) << 3)) * 72 + ((lane >> 3) & 1) * 8) << 1);
    const uint32_t B_LO = 9216, MF = 2304;

    ld_stage(sb, A, lda, Bh, Bl, ldb, rowBase, colBase, 0, Nrows, tid, dual);
    CP_COMMIT();

    for (int kt = 0; kt < Ktiles; kt++) {
        uint32_t stb = sb + (uint32_t)(kt & 1) * STG;
        if (kt + 1 < Ktiles) {
            ld_stage(sb + (uint32_t)((kt + 1) & 1) * STG, A, lda, Bh, Bl, ldb,
                     rowBase, colBase, (kt + 1) * 64, Nrows, tid, dual);
            CP_COMMIT();
            CP_WAIT1();
        } else {
            CP_WAIT0();
        }
        __syncthreads();

        uint32_t aA = stb + offA;
        uint32_t aB = stb + offB;
#pragma unroll
        for (int ks = 0; ks < 4; ks++) {
            uint32_t kso = ks * 32;
            uint32_t bh[4][2], bl[4][2];
            LDSM4(bh[0][0], bh[0][1], bh[1][0], bh[1][1], aB + kso);
            LDSM4(bh[2][0], bh[2][1], bh[3][0], bh[3][1], aB + MF + kso);
            if (dual) {
                LDSM4(bl[0][0], bl[0][1], bl[1][0], bl[1][1], aB + B_LO + kso);
                LDSM4(bl[2][0], bl[2][1], bl[3][0], bl[3][1], aB + B_LO + MF + kso);
            }
#pragma unroll
            for (int mf = 0; mf < 2; mf++) {
                uint32_t ar[4];
                LDSM4(ar[0], ar[1], ar[2], ar[3], aA + mf * MF + kso);
#pragma unroll
                for (int nf = 0; nf < 4; nf++) {
                    mma16(acc[mf][nf], ar, bh[nf]);
                    if (dual) mma16(acc[mf][nf], ar, bl[nf]);
                }
            }
        }
        __syncthreads();
    }

    // epilogue
    int gid = lane >> 2, tig = lane & 3;
#pragma unroll
    for (int mf = 0; mf < 2; mf++) {
#pragma unroll
        for (int half = 0; half < 2; half++) {
            int r = rowBase + wm * 32 + mf * 16 + gid + half * 8;
            if (r >= Nrows) continue;
            int bidx = (mode == 3) ? batch[r] : 0;
#pragma unroll
            for (int nf = 0; nf < 4; nf++) {
                int c0 = colBase + wn * 32 + nf * 8 + tig * 2;
                float v0 = acc[mf][nf][half * 2];
                float v1 = acc[mf][nf][half * 2 + 1];
                if (mode == 2) {
                    float o0 = 0.f, o1 = 0.f;
                    if (c0 < HID)
                        o0 = fmaxf(fmaf(v0 + bias[c0], scale[c0], shift[c0]), 0.f);
                    if (c0 + 1 < HID)
                        o1 = fmaxf(fmaf(v1 + bias[c0 + 1], scale[c0 + 1], shift[c0 + 1]), 0.f);
                    *(__half2*)(O + (size_t)r * LDAH + c0) =
                        __halves2half2(__float2half_rn(o0), __float2half_rn(o1));
                } else {
                    if (c0 < HID)
                        atomicMax(&pool[bidx * HID + c0], enc_f(v0 + bias[c0]));
                    if (c0 + 1 < HID)
                        atomicMax(&pool[bidx * HID + c0 + 1], enc_f(v1 + bias[c0 + 1]));
                }
            }
        }
    }
}

// fp16 aggregation: z[n] = dn * sum_e w_e * h[src_e] + dn^2 * h[n]   (half2 lanes)
__global__ void k_agg16(const __half* __restrict__ src, int N) {
    int n = blockIdx.x;
    int c0 = threadIdx.x * 2;   // 0..190 (96 threads cover 192 cols)
    int s0 = g_offs[n], s1 = g_offs[n + 1];
    float a0 = 0.f, a1 = 0.f;
    int e = s0;
    for (; e + 4 <= s1; e += 4) {
        int2 e0 = g_csr[e],     e1 = g_csr[e + 1];
        int2 e2 = g_csr[e + 2], e3 = g_csr[e + 3];
        float2 p0 = __half22float2(*(const __half2*)(src + (size_t)e0.x * LDAH + c0));
        float2 p1 = __half22float2(*(const __half2*)(src + (size_t)e1.x * LDAH + c0));
        float2 p2 = __half22float2(*(const __half2*)(src + (size_t)e2.x * LDAH + c0));
        float2 p3 = __half22float2(*(const __half2*)(src + (size_t)e3.x * LDAH + c0));
        float w0 = __int_as_float(e0.y), w1 = __int_as_float(e1.y);
        float w2 = __int_as_float(e2.y), w3 = __int_as_float(e3.y);
        a0 += w0 * p0.x + w1 * p1.x + w2 * p2.x + w3 * p3.x;
        a1 += w0 * p0.y + w1 * p1.y + w2 * p2.y + w3 * p3.y;
    }
    for (; e < s1; ++e) {
        int2 ed = g_csr[e];
        float w = __int_as_float(ed.y);
        float2 p = __half22float2(*(const __half2*)(src + (size_t)ed.x * LDAH + c0));
        a0 += w * p.x;
        a1 += w * p.y;
    }
    float dn = g_dis[n];
    float2 self = __half22float2(*(const __half2*)(src + (size_t)n * LDAH + c0));
    float v0 = dn * a0 + dn * dn * self.x;
    float v1 = dn * a1 + dn * dn * self.y;
    *(__half2*)(g_Z + (size_t)n * LDZ + c0) = __floats2half2_rn(v0, v1);
}

__global__ void k_finalize(const float* __restrict__ Wout,
                           const float* __restrict__ bout,
                           float* __restrict__ out, int G) {
    int g = blockIdx.x, t = threadIdx.x;
    __shared__ float red[256];
    float p = 0.f;
    for (int c = t; c < HID; c += 256)
        p += dec_f(g_pool[g * HID + c]) * Wout[c];
    red[t] = p;
    __syncthreads();
    for (int o = 128; o; o >>= 1) {
        if (t < o) red[t] += red[t + o];
        __syncthreads();
    }
    if (t == 0) out[g] = red[0] + bout[0];
}

// ---------------- host launcher ----------------
extern "C" void kernel_launch(void* const* d_in, const int* in_sizes, int n_in,
                              void* d_out, int out_size) {
    const float* x     = (const float*)d_in[0];
    const int*   ei    = (const int*)  d_in[1];
    const int*   batch = (const int*)  d_in[2];
    const float* W0    = (const float*)d_in[3];
    const float* b0    = (const float*)d_in[4];
    const float* W_h   = (const float*)d_in[5];
    const float* b_h   = (const float*)d_in[6];
    const float* bn_g  = (const float*)d_in[7];
    const float* bn_b  = (const float*)d_in[8];
    const float* bn_m  = (const float*)d_in[9];
    const float* bn_v  = (const float*)d_in[10];
    const float* W_jk  = (const float*)d_in[11];
    const float* b_jk  = (const float*)d_in[12];
    const float* W_out = (const float*)d_in[13];
    const float* b_out = (const float*)d_in[14];
    float* out = (float*)d_out;

    int N = in_sizes[0] / INCH;
    int E = in_sizes[1] / 2;
    int G = out_size;
    int SB = (N + 255) / 256;
    int EB = (E + 255) / 256;
    int poolBlks = (G * HID + 255) / 256;

    cudaFuncSetAttribute(k_mma, cudaFuncAttributeMaxDynamicSharedMemorySize, SMEM_BYTES);

    __half *a0, *axs, *zz, *w0h, *w0l, *whh, *whl, *wjh;
    cudaGetSymbolAddress((void**)&a0,  g_A0);
    cudaGetSymbolAddress((void**)&axs, g_Axs);
    cudaGetSymbolAddress((void**)&zz,  g_Z);
    cudaGetSymbolAddress((void**)&w0h, g_W0th);
    cudaGetSymbolAddress((void**)&w0l, g_W0tl);
    cudaGetSymbolAddress((void**)&whh, g_Whth);
    cudaGetSymbolAddress((void**)&whl, g_Whtl);
    cudaGetSymbolAddress((void**)&wjh, g_Wjkth);
    float *bns, *bnh;
    cudaGetSymbolAddress((void**)&bns, g_bnscale);
    cudaGetSymbolAddress((void**)&bnh, g_bnshift);
    unsigned* pool;
    cudaGetSymbolAddress((void**)&pool, g_pool);

    // merged count + weight prep + bn + pool init
    k_prep<<<EB + 1059 + poolBlks, 256>>>(ei, E, EB, W0, W_h, W_jk,
                                          bn_g, bn_b, bn_m, bn_v, G);
    k_scan_blk<<<SB, 256>>>(N);
    k_scan_add<<<SB, 256>>>(N, SB);
    k_fill<<<(E + 255) / 256, 256>>>(ei, E);
    k_aggregate_x<<<(N * 32 + 255) / 256, 256>>>(x, N);

    dim3 grid(3, (N + 127) / 128);

    // layer 0: (Âx)@W0 -> bias+bn0+relu -> fp16 concat cols [0,192)
    k_mma<<<grid, 256, SMEM_BYTES>>>(a0, 64, w0h, w0l, 64, N, 1,
                                     axs, b0, bns, bnh,
                                     (const int*)0, (unsigned*)0, 2, 1);
    // hidden layers 1..3: aggregate fp16 activations first, then GEMM+epilogue
    for (int i = 1; i <= 3; i++) {
        k_agg16<<<N, 96>>>(axs + (size_t)(i - 1) * 192, N);
        k_mma<<<grid, 256, SMEM_BYTES>>>(zz, LDZ,
                                         whh + (size_t)(i - 1) * 36864,
                                         whl + (size_t)(i - 1) * 36864, 192,
                                         N, 3,
                                         axs + (size_t)i * 192,
                                         b_h + (size_t)(i - 1) * HID,
                                         bns + i * HID, bnh + i * HID,
                                         (const int*)0, (unsigned*)0, 2, 1);
    }
    // JK GEMM fused with max-pool (hi-only weights: last layer, error doesn't compound)
    k_mma<<<grid, 256, SMEM_BYTES>>>(axs, LDAH, wjh, wjh, 768, N, 12,
                                     (__half*)0,
                                     b_jk, (const float*)0, (const float*)0,
                                     batch, pool, 3, 0);

    k_finalize<<<G, 256>>>(W_out, b_out, out, G);
}

// round 10
// speedup vs baseline: 1.3882x; 1.0108x over previous
#include <cuda_runtime.h>
#include <cuda_fp16.h>
#include <cstdint>
#include <math.h>

#define NMAX   25000
#define EMAX   400000
#define GMAX   1000
#define HID    185
#define INCH   9
#define LDAH   768      // padded concat width (4*192)
#define LDZ    192      // aggregated-activation row stride

// ---------------- scratch ----------------
__device__ int      g_cnt[NMAX];          // BSS zero; self-cleaned each call
__device__ int      g_part[NMAX];
__device__ int      g_bsum[128];
__device__ int      g_offs[NMAX + 1];
__device__ int      g_cursor[NMAX];
__device__ float    g_dis[NMAX];
__device__ __align__(16) int2 g_csr[EMAX];   // (src, weight bits)
__device__ __align__(16) __half g_A0[NMAX * 16];        // layer0 aggregated input (fp16, 16-wide)
__device__ __align__(16) __half g_Axs[NMAX * LDAH];     // concat activations (fp16)
__device__ __align__(16) __half g_Z[NMAX * LDZ];        // aggregated activations (fp16)
__device__ __align__(16) __half g_W0th[192 * 16];
__device__ __align__(16) __half g_W0tl[192 * 16];
__device__ __align__(16) __half g_Whth[3 * 192 * 192];
__device__ __align__(16) __half g_Whtl[3 * 192 * 192];
__device__ __align__(16) __half g_Wjkth[192 * 768];
__device__ unsigned g_pool[GMAX * HID];
__device__ float    g_bnscale[4 * HID];
__device__ float    g_bnshift[4 * HID];

// ---------------- helpers ----------------
__device__ __forceinline__ unsigned enc_f(float f) {
    unsigned u = __float_as_uint(f);
    return (u & 0x80000000u) ? ~u : (u | 0x80000000u);
}
__device__ __forceinline__ float dec_f(unsigned e) {
    return (e & 0x80000000u) ? __uint_as_float(e & 0x7FFFFFFFu) : __uint_as_float(~e);
}
__device__ __forceinline__ void split_h(float v, __half& h, __half& l) {
    h = __float2half_rn(v);
    l = __float2half_rn(v - __half2float(h));
}
__device__ __forceinline__ uint32_t smem_u32(const void* p) {
    uint32_t a;
    asm("{ .reg .u64 t; cvta.to.shared.u64 t, %1; cvt.u32.u64 %0, t; }" : "=r"(a) : "l"(p));
    return a;
}
#define LDSM4(r0, r1, r2, r3, addr) \
    asm volatile("ldmatrix.sync.aligned.m8n8.x4.shared.b16 {%0,%1,%2,%3}, [%4];" \
        : "=r"(r0), "=r"(r1), "=r"(r2), "=r"(r3) : "r"(addr))
__device__ __forceinline__ void mma16(float* c, const uint32_t* a, const uint32_t* b) {
    asm volatile("mma.sync.aligned.m16n8k16.row.col.f32.f16.f16.f32 "
        "{%0,%1,%2,%3}, {%4,%5,%6,%7}, {%8,%9}, {%0,%1,%2,%3};"
        : "+f"(c[0]), "+f"(c[1]), "+f"(c[2]), "+f"(c[3])
        : "r"(a[0]), "r"(a[1]), "r"(a[2]), "r"(a[3]), "r"(b[0]), "r"(b[1]));
}
#define CP16(dst, src, sz) \
    asm volatile("cp.async.cg.shared.global [%0], [%1], 16, %2;" \
        :: "r"(dst), "l"(src), "r"(sz) : "memory")
#define CP_COMMIT() asm volatile("cp.async.commit_group;" ::: "memory")
#define CP_WAIT0()  asm volatile("cp.async.wait_group 0;" ::: "memory")
#define CP_WAIT1()  asm volatile("cp.async.wait_group 1;" ::: "memory")

// ---------------- merged: edge count + weight prep + BN fold + pool init ----
// blocks: [0,EB) count | [EB,+12) W0 | [+12,+444) Wh | [+444,+1020) Wjk
//         [+1020,+1023) bn | [+1023, +1023+poolBlks) pool
__global__ void k_prep(const int* __restrict__ ei, int E, int EB,
                       const float* __restrict__ W0, const float* __restrict__ Wh,
                       const float* __restrict__ Wjk,
                       const float* __restrict__ gamma, const float* __restrict__ beta,
                       const float* __restrict__ mean, const float* __restrict__ var,
                       int G) {
    int t = threadIdx.x;
    if (blockIdx.x < EB) {
        int e = blockIdx.x * 256 + t;
        if (e < E) atomicAdd(&g_cnt[ei[E + e]], 1);
        return;
    }
    int b = blockIdx.x - EB;
    if (b < 12) {
        int idx = b * 256 + t;   // 192*16 = 3072
        int n = idx >> 4, k = idx & 15;
        float v = (n < HID && k < INCH) ? W0[k * HID + n] : 0.f;
        __half h, l; split_h(v, h, l);
        g_W0th[idx] = h; g_W0tl[idx] = l;
    } else if (b < 444) {
        int q = b - 12;
        int L = q / 144;
        int idx = (q - L * 144) * 256 + t;
        int n = idx / 192, k = idx % 192;
        float v = (n < HID && k < HID) ? Wh[(size_t)L * HID * HID + k * HID + n] : 0.f;
        __half h, l; split_h(v, h, l);
        g_Whth[L * 36864 + idx] = h; g_Whtl[L * 36864 + idx] = l;
    } else if (b < 1020) {
        int idx = (b - 444) * 256 + t;
        int n = idx / 768, k = idx % 768;
        int layer = k / 192, c = k % 192;
        float v = (n < HID && c < HID) ? Wjk[(size_t)(layer * HID + c) * HID + n] : 0.f;
        g_Wjkth[idx] = __float2half_rn(v);
    } else if (b < 1023) {
        int i = (b - 1020) * 256 + t;
        if (i < 4 * HID) {
            float sc = gamma[i] * rsqrtf(var[i] + 1e-5f);
            g_bnscale[i] = sc;
            g_bnshift[i] = beta[i] - mean[i] * sc;
        }
    } else {
        int i = (b - 1023) * 256 + t;
        if (i < G * HID) g_pool[i] = 0x007FFFFFu;    // enc(-inf)
    }
}

__global__ void k_scan_blk(int N) {
    __shared__ int sh[256];
    int i = blockIdx.x * 256 + threadIdx.x;
    int v = (i < N) ? g_cnt[i] : 0;
    sh[threadIdx.x] = v;
    __syncthreads();
    for (int o = 1; o < 256; o <<= 1) {
        int a = (threadIdx.x >= o) ? sh[threadIdx.x - o] : 0;
        __syncthreads();
        sh[threadIdx.x] += a;
        __syncthreads();
    }
    if (i < N) g_part[i] = sh[threadIdx.x] - v;
    if (threadIdx.x == 255) g_bsum[blockIdx.x] = sh[255];
}
__global__ void k_scan_add(int N, int SB) {
    __shared__ int sh[128];
    int t = threadIdx.x;
    if (t < 128) sh[t] = (t < SB) ? g_bsum[t] : 0;
    __syncthreads();
    for (int o = 1; o < 128; o <<= 1) {
        int a = (t >= o && t < 128) ? sh[t - o] : 0;
        __syncthreads();
        if (t < 128) sh[t] += a;
        __syncthreads();
    }
    int i = blockIdx.x * 256 + t;
    if (i >= N) return;
    int pre = sh[blockIdx.x] - g_bsum[blockIdx.x];
    int off = g_part[i] + pre;
    int c = g_cnt[i];
    g_cnt[i] = 0;
    g_offs[i] = off;
    g_cursor[i] = off;
    if (i == N - 1) g_offs[N] = off + c;
    g_dis[i] = rsqrtf((float)c + 1.0f);
}
__global__ void k_fill(const int* __restrict__ ei, int E) {
    int e = blockIdx.x * blockDim.x + threadIdx.x;
    if (e >= E) return;
    int s = ei[e], d = ei[E + e];
    int p = atomicAdd(&g_cursor[d], 1);
    g_csr[p] = make_int2(s, __float_as_int(g_dis[s]));
}

// aggregate raw x (9 ch) -> fp16 A0 [N x 16]
__global__ void k_aggregate_x(const float* __restrict__ x, int N) {
    int warp = (blockIdx.x * blockDim.x + threadIdx.x) >> 5;
    int lane = threadIdx.x & 31;
    if (warp >= N) return;
    int n = warp;
    int s0 = g_offs[n], s1 = g_offs[n + 1];
    float acc[INCH];
#pragma unroll
    for (int c = 0; c < INCH; c++) acc[c] = 0.f;
    for (int e = s0 + lane; e < s1; e += 32) {
        int2 ed = g_csr[e];
        float w = __int_as_float(ed.y);
#pragma unroll
        for (int c = 0; c < INCH; c++) acc[c] += w * x[ed.x * INCH + c];
    }
#pragma unroll
    for (int c = 0; c < INCH; c++)
#pragma unroll
        for (int o = 16; o; o >>= 1)
            acc[c] += __shfl_xor_sync(0xffffffffu, acc[c], o);
    if (lane == 0) {
        float dn = g_dis[n];
#pragma unroll
        for (int c = 0; c < INCH; c++) {
            float v = dn * acc[c] + dn * dn * x[n * INCH + c];
            g_A0[n * 16 + c] = __float2half_rn(v);
        }
    }
    if (lane < 16 - INCH)
        g_A0[n * 16 + INCH + lane] = __float2half_rn(0.f);
}

// ---------------- fp16 GEMM (x2 or x1 weight split), cp.async double-buffered
// stage (bytes): sA 0 (128x72h = 18432), sBh 18432 (64x72h = 9216), sBl 27648
#define STG 36864
#define SMEM_BYTES (2 * STG)

__device__ __forceinline__ void ld_stage(
    uint32_t smb,
    const __half* __restrict__ A, int lda,
    const __half* __restrict__ Bh, const __half* __restrict__ Bl, int ldb,
    int rowBase, int colBase, int k0, int Nrows, int tid, int dual, int kw16) {
    if (kw16) {
        // A: 128 rows x 16 halves = 256 16B-chunks
        int r = tid >> 1, j = tid & 1;
        int gr = rowBase + r;
        int sz = (gr < Nrows) ? 16 : 0;
        int grc = min(gr, Nrows - 1);
        CP16(smb + r * 144 + j * 16, A + (size_t)grc * lda + j * 8, sz);
        // B: 64 rows x 16 halves = 128 chunks (hi [+lo])
        if (tid < 128) {
            int n = tid >> 1, jb = tid & 1;
            size_t go = (size_t)(colBase + n) * ldb + jb * 8;
            uint32_t d = smb + 18432 + n * 144 + jb * 16;
            CP16(d, Bh + go, 16);
            if (dual) CP16(d + 9216, Bl + go, 16);
        }
        return;
    }
#pragma unroll
    for (int s = 0; s < 4; s++) {
        int idx = tid + s * 256;
        int r = idx >> 3, j = idx & 7;
        int gr = rowBase + r;
        int sz = (gr < Nrows) ? 16 : 0;
        int grc = min(gr, Nrows - 1);
        size_t go = (size_t)grc * lda + k0 + j * 8;
        CP16(smb + r * 144 + j * 16, A + go, sz);
    }
#pragma unroll
    for (int s = 0; s < 2; s++) {
        int idx = tid + s * 256;
        int n = idx >> 3, j = idx & 7;
        size_t go = (size_t)(colBase + n) * ldb + k0 + j * 8;
        uint32_t d = smb + 18432 + n * 144 + j * 16;
        CP16(d, Bh + go, 16);
        if (dual) CP16(d + 9216, Bl + go, 16);
    }
}

// mode 2: bias+bn+relu -> fp16 half2 into O     mode 3: bias -> smem-staged max-pool
// dual: 1 = hi+lo weight split (2 MMAs/step), 0 = hi only
// ksteps: k-steps per 64-wide tile (4) or 1 for the 16-wide layer-0 tile (kw16=1)
__global__ void __launch_bounds__(256)
k_mma(const __half* __restrict__ A, int lda,
      const __half* __restrict__ Bh, const __half* __restrict__ Bl, int ldb,
      int Nrows, int Ktiles,
      __half* __restrict__ O,
      const float* __restrict__ bias, const float* __restrict__ scale,
      const float* __restrict__ shift,
      const int* __restrict__ batch, unsigned* __restrict__ pool,
      int mode, int dual, int ksteps, int kw16) {
    extern __shared__ __align__(16) char smch[];
    uint32_t sb = smem_u32(smch);

    int tid = threadIdx.x, lane = tid & 31, w = tid >> 5;
    int wm = w & 3, wn = w >> 2;
    int rowBase = blockIdx.y * 128, colBase = blockIdx.x * 64;

    float acc[2][4][4];
#pragma unroll
    for (int i = 0; i < 2; i++)
#pragma unroll
        for (int j = 0; j < 4; j++)
#pragma unroll
            for (int q = 0; q < 4; q++) acc[i][j][q] = 0.f;

    const uint32_t offA = (uint32_t)((wm * 32 + (lane & 15)) * 72 + (lane >> 4) * 8) << 1;
    const uint32_t offB = 18432u +
        ((uint32_t)((wn * 32 + (lane & 7) + ((lane >> 4) << 3)) * 72 + ((lane >> 3) & 1) * 8) << 1);
    const uint32_t B_LO = 9216, MF = 2304;

    ld_stage(sb, A, lda, Bh, Bl, ldb, rowBase, colBase, 0, Nrows, tid, dual, kw16);
    CP_COMMIT();

    for (int kt = 0; kt < Ktiles; kt++) {
        uint32_t stb = sb + (uint32_t)(kt & 1) * STG;
        if (kt + 1 < Ktiles) {
            ld_stage(sb + (uint32_t)((kt + 1) & 1) * STG, A, lda, Bh, Bl, ldb,
                     rowBase, colBase, (kt + 1) * 64, Nrows, tid, dual, kw16);
            CP_COMMIT();
            CP_WAIT1();
        } else {
            CP_WAIT0();
        }
        __syncthreads();

        uint32_t aA = stb + offA;
        uint32_t aB = stb + offB;
        for (int ks = 0; ks < ksteps; ks++) {
            uint32_t kso = ks * 32;
            uint32_t bh[4][2], bl[4][2];
            LDSM4(bh[0][0], bh[0][1], bh[1][0], bh[1][1], aB + kso);
            LDSM4(bh[2][0], bh[2][1], bh[3][0], bh[3][1], aB + MF + kso);
            if (dual) {
                LDSM4(bl[0][0], bl[0][1], bl[1][0], bl[1][1], aB + B_LO + kso);
                LDSM4(bl[2][0], bl[2][1], bl[3][0], bl[3][1], aB + B_LO + MF + kso);
            }
#pragma unroll
            for (int mf = 0; mf < 2; mf++) {
                uint32_t ar[4];
                LDSM4(ar[0], ar[1], ar[2], ar[3], aA + mf * MF + kso);
#pragma unroll
                for (int nf = 0; nf < 4; nf++) {
                    mma16(acc[mf][nf], ar, bh[nf]);
                    if (dual) mma16(acc[mf][nf], ar, bl[nf]);
                }
            }
        }
        __syncthreads();
    }

    int gid = lane >> 2, tig = lane & 3;
    if (mode == 2) {
#pragma unroll
        for (int mf = 0; mf < 2; mf++) {
#pragma unroll
            for (int half = 0; half < 2; half++) {
                int r = rowBase + wm * 32 + mf * 16 + gid + half * 8;
                if (r >= Nrows) continue;
#pragma unroll
                for (int nf = 0; nf < 4; nf++) {
                    int c0 = colBase + wn * 32 + nf * 8 + tig * 2;
                    float v0 = acc[mf][nf][half * 2];
                    float v1 = acc[mf][nf][half * 2 + 1];
                    float o0 = 0.f, o1 = 0.f;
                    if (c0 < HID)
                        o0 = fmaxf(fmaf(v0 + bias[c0], scale[c0], shift[c0]), 0.f);
                    if (c0 + 1 < HID)
                        o1 = fmaxf(fmaf(v1 + bias[c0 + 1], scale[c0 + 1], shift[c0 + 1]), 0.f);
                    *(__half2*)(O + (size_t)r * LDAH + c0) =
                        __halves2half2(__float2half_rn(o0), __float2half_rn(o1));
                }
            }
        }
    } else {
        // mode 3: smem-staged max-pool (batch is sorted; tile spans <= 128 graphs)
        unsigned* spool = (unsigned*)smch;
        int g0 = batch[rowBase];
        int rlast = min(rowBase + 127, Nrows - 1);
        int range = batch[rlast] - g0 + 1;   // <= 128
        for (int i = tid; i < range * 64; i += 256) spool[i] = 0x007FFFFFu;
        __syncthreads();
#pragma unroll
        for (int mf = 0; mf < 2; mf++) {
#pragma unroll
            for (int half = 0; half < 2; half++) {
                int r = rowBase + wm * 32 + mf * 16 + gid + half * 8;
                if (r >= Nrows) continue;
                int bloc = (batch[r] - g0) * 64;
#pragma unroll
                for (int nf = 0; nf < 4; nf++) {
                    int c0 = colBase + wn * 32 + nf * 8 + tig * 2;
                    float v0 = acc[mf][nf][half * 2];
                    float v1 = acc[mf][nf][half * 2 + 1];
                    int cl = wn * 32 + nf * 8 + tig * 2;
                    if (c0 < HID)
                        atomicMax(&spool[bloc + cl], enc_f(v0 + bias[c0]));
                    if (c0 + 1 < HID)
                        atomicMax(&spool[bloc + cl + 1], enc_f(v1 + bias[c0 + 1]));
                }
            }
        }
        __syncthreads();
        for (int i = tid; i < range * 64; i += 256) {
            int bgr = i >> 6;
            int c = colBase + (i & 63);
            if (c < HID)
                atomicMax(&pool[(g0 + bgr) * HID + c], spool[i]);
        }
    }
}

// fp16 aggregation: z[n] = dn * sum_e w_e * h[src_e] + dn^2 * h[n]   (half2 lanes)
__global__ void k_agg16(const __half* __restrict__ src, int N) {
    int n = blockIdx.x;
    int c0 = threadIdx.x * 2;   // 0..190 (96 threads cover 192 cols)
    int s0 = g_offs[n], s1 = g_offs[n + 1];
    float a0 = 0.f, a1 = 0.f;
    int e = s0;
    for (; e + 4 <= s1; e += 4) {
        int2 e0 = g_csr[e],     e1 = g_csr[e + 1];
        int2 e2 = g_csr[e + 2], e3 = g_csr[e + 3];
        float2 p0 = __half22float2(*(const __half2*)(src + (size_t)e0.x * LDAH + c0));
        float2 p1 = __half22float2(*(const __half2*)(src + (size_t)e1.x * LDAH + c0));
        float2 p2 = __half22float2(*(const __half2*)(src + (size_t)e2.x * LDAH + c0));
        float2 p3 = __half22float2(*(const __half2*)(src + (size_t)e3.x * LDAH + c0));
        float w0 = __int_as_float(e0.y), w1 = __int_as_float(e1.y);
        float w2 = __int_as_float(e2.y), w3 = __int_as_float(e3.y);
        a0 += w0 * p0.x + w1 * p1.x + w2 * p2.x + w3 * p3.x;
        a1 += w0 * p0.y + w1 * p1.y + w2 * p2.y + w3 * p3.y;
    }
    for (; e < s1; ++e) {
        int2 ed = g_csr[e];
        float w = __int_as_float(ed.y);
        float2 p = __half22float2(*(const __half2*)(src + (size_t)ed.x * LDAH + c0));
        a0 += w * p.x;
        a1 += w * p.y;
    }
    float dn = g_dis[n];
    float2 self = __half22float2(*(const __half2*)(src + (size_t)n * LDAH + c0));
    float v0 = dn * a0 + dn * dn * self.x;
    float v1 = dn * a1 + dn * dn * self.y;
    *(__half2*)(g_Z + (size_t)n * LDZ + c0) = __floats2half2_rn(v0, v1);
}

__global__ void k_finalize(const float* __restrict__ Wout,
                           const float* __restrict__ bout,
                           float* __restrict__ out, int G) {
    int g = blockIdx.x, t = threadIdx.x;
    __shared__ float red[256];
    float p = 0.f;
    for (int c = t; c < HID; c += 256)
        p += dec_f(g_pool[g * HID + c]) * Wout[c];
    red[t] = p;
    __syncthreads();
    for (int o = 128; o; o >>= 1) {
        if (t < o) red[t] += red[t + o];
        __syncthreads();
    }
    if (t == 0) out[g] = red[0] + bout[0];
}

// ---------------- host launcher ----------------
extern "C" void kernel_launch(void* const* d_in, const int* in_sizes, int n_in,
                              void* d_out, int out_size) {
    const float* x     = (const float*)d_in[0];
    const int*   ei    = (const int*)  d_in[1];
    const int*   batch = (const int*)  d_in[2];
    const float* W0    = (const float*)d_in[3];
    const float* b0    = (const float*)d_in[4];
    const float* W_h   = (const float*)d_in[5];
    const float* b_h   = (const float*)d_in[6];
    const float* bn_g  = (const float*)d_in[7];
    const float* bn_b  = (const float*)d_in[8];
    const float* bn_m  = (const float*)d_in[9];
    const float* bn_v  = (const float*)d_in[10];
    const float* W_jk  = (const float*)d_in[11];
    const float* b_jk  = (const float*)d_in[12];
    const float* W_out = (const float*)d_in[13];
    const float* b_out = (const float*)d_in[14];
    float* out = (float*)d_out;

    int N = in_sizes[0] / INCH;
    int E = in_sizes[1] / 2;
    int G = out_size;
    int SB = (N + 255) / 256;
    int EB = (E + 255) / 256;
    int poolBlks = (G * HID + 255) / 256;

    cudaFuncSetAttribute(k_mma, cudaFuncAttributeMaxDynamicSharedMemorySize, SMEM_BYTES);

    __half *a0, *axs, *zz, *w0h, *w0l, *whh, *whl, *wjh;
    cudaGetSymbolAddress((void**)&a0,  g_A0);
    cudaGetSymbolAddress((void**)&axs, g_Axs);
    cudaGetSymbolAddress((void**)&zz,  g_Z);
    cudaGetSymbolAddress((void**)&w0h, g_W0th);
    cudaGetSymbolAddress((void**)&w0l, g_W0tl);
    cudaGetSymbolAddress((void**)&whh, g_Whth);
    cudaGetSymbolAddress((void**)&whl, g_Whtl);
    cudaGetSymbolAddress((void**)&wjh, g_Wjkth);
    float *bns, *bnh;
    cudaGetSymbolAddress((void**)&bns, g_bnscale);
    cudaGetSymbolAddress((void**)&bnh, g_bnshift);
    unsigned* pool;
    cudaGetSymbolAddress((void**)&pool, g_pool);

    // merged count + weight prep + bn + pool init
    k_prep<<<EB + 1023 + poolBlks, 256>>>(ei, E, EB, W0, W_h, W_jk,
                                          bn_g, bn_b, bn_m, bn_v, G);
    k_scan_blk<<<SB, 256>>>(N);
    k_scan_add<<<SB, 256>>>(N, SB);
    k_fill<<<(E + 255) / 256, 256>>>(ei, E);
    k_aggregate_x<<<(N * 32 + 255) / 256, 256>>>(x, N);

    dim3 grid(3, (N + 127) / 128);

    // layer 0: (Âx)@W0 -> bias+bn0+relu -> fp16 concat cols [0,192)  (16-wide K)
    k_mma<<<grid, 256, SMEM_BYTES>>>(a0, 16, w0h, w0l, 16, N, 1,
                                     axs, b0, bns, bnh,
                                     (const int*)0, (unsigned*)0, 2, 1, 1, 1);
    // hidden layers 1..3: aggregate fp16 activations first, then GEMM+epilogue
    for (int i = 1; i <= 3; i++) {
        k_agg16<<<N, 96>>>(axs + (size_t)(i - 1) * 192, N);
        k_mma<<<grid, 256, SMEM_BYTES>>>(zz, LDZ,
                                         whh + (size_t)(i - 1) * 36864,
                                         whl + (size_t)(i - 1) * 36864, 192,
                                         N, 3,
                                         axs + (size_t)i * 192,
                                         b_h + (size_t)(i - 1) * HID,
                                         bns + i * HID, bnh + i * HID,
                                         (const int*)0, (unsigned*)0, 2, 1, 4, 0);
    }
    // JK GEMM fused with smem-staged max-pool (hi-only weights: last layer)
    k_mma<<<grid, 256, SMEM_BYTES>>>(axs, LDAH, wjh, wjh, 768, N, 12,
                                     (__half*)0,
                                     b_jk, (const float*)0, (const float*)0,
                                     batch, pool, 3, 0, 4, 0);

    k_finalize<<<G, 256>>>(W_out, b_out, out, G);
}

// round 12
// speedup vs baseline: 1.4045x; 1.0117x over previous
#include <cuda_runtime.h>
#include <cuda_fp16.h>
#include <cstdint>
#include <math.h>

#define NMAX   25000
#define EMAX   400000
#define GMAX   1000
#define HID    185
#define INCH   9
#define LDAH   768      // padded concat width (4*192)
#define LDZ    192      // aggregated-activation row stride

// ---------------- scratch ----------------
__device__ int      g_cnt[NMAX];          // BSS zero; self-cleaned each call
__device__ int      g_part[NMAX];
__device__ int      g_bsum[128];
__device__ int      g_offs[NMAX + 1];
__device__ float    g_dis[NMAX];
__device__ int      g_erank[EMAX];
__device__ __align__(16) int2 g_csr[EMAX];   // (src, weight bits)
__device__ __align__(16) __half g_A0[NMAX * 16];
__device__ __align__(16) __half g_Axs[NMAX * LDAH];
__device__ __align__(16) __half g_Z[NMAX * LDZ];
__device__ __align__(16) __half g_W0th[192 * 16];
__device__ __align__(16) __half g_W0tl[192 * 16];
__device__ __align__(16) __half g_Whth[3 * 192 * 192];
__device__ __align__(16) __half g_Whtl[3 * 192 * 192];
__device__ __align__(16) __half g_Wjkth[192 * 768];
__device__ unsigned g_pool[GMAX * HID];
__device__ float    g_bnscale[4 * HID];
__device__ float    g_bnshift[4 * HID];

// ---------------- helpers ----------------
__device__ __forceinline__ unsigned enc_f(float f) {
    unsigned u = __float_as_uint(f);
    return (u & 0x80000000u) ? ~u : (u | 0x80000000u);
}
__device__ __forceinline__ float dec_f(unsigned e) {
    return (e & 0x80000000u) ? __uint_as_float(e & 0x7FFFFFFFu) : __uint_as_float(~e);
}
__device__ __forceinline__ void split_h(float v, __half& h, __half& l) {
    h = __float2half_rn(v);
    l = __float2half_rn(v - __half2float(h));
}
__device__ __forceinline__ uint32_t smem_u32(const void* p) {
    uint32_t a;
    asm("{ .reg .u64 t; cvta.to.shared.u64 t, %1; cvt.u32.u64 %0, t; }" : "=r"(a) : "l"(p));
    return a;
}
#define LDSM4(r0, r1, r2, r3, addr) \
    asm volatile("ldmatrix.sync.aligned.m8n8.x4.shared.b16 {%0,%1,%2,%3}, [%4];" \
        : "=r"(r0), "=r"(r1), "=r"(r2), "=r"(r3) : "r"(addr))
__device__ __forceinline__ void mma16(float* c, const uint32_t* a, const uint32_t* b) {
    asm volatile("mma.sync.aligned.m16n8k16.row.col.f32.f16.f16.f32 "
        "{%0,%1,%2,%3}, {%4,%5,%6,%7}, {%8,%9}, {%0,%1,%2,%3};"
        : "+f"(c[0]), "+f"(c[1]), "+f"(c[2]), "+f"(c[3])
        : "r"(a[0]), "r"(a[1]), "r"(a[2]), "r"(a[3]), "r"(b[0]), "r"(b[1]));
}
#define CP16(dst, src, sz) \
    asm volatile("cp.async.cg.shared.global [%0], [%1], 16, %2;" \
        :: "r"(dst), "l"(src), "r"(sz) : "memory")
#define CP_COMMIT() asm volatile("cp.async.commit_group;" ::: "memory")
#define CP_WAIT0()  asm volatile("cp.async.wait_group 0;" ::: "memory")
#define CP_WAIT1()  asm volatile("cp.async.wait_group 1;" ::: "memory")

// ---------------- merged: edge count+rank + weight prep + BN fold + pool init
__global__ void k_prep(const int* __restrict__ ei, int E, int EB,
                       const float* __restrict__ W0, const float* __restrict__ Wh,
                       const float* __restrict__ Wjk,
                       const float* __restrict__ gamma, const float* __restrict__ beta,
                       const float* __restrict__ mean, const float* __restrict__ var,
                       int G) {
    int t = threadIdx.x;
    if (blockIdx.x < EB) {
        int e = blockIdx.x * 256 + t;
        if (e < E) g_erank[e] = atomicAdd(&g_cnt[ei[E + e]], 1);
        return;
    }
    int b = blockIdx.x - EB;
    if (b < 12) {
        int idx = b * 256 + t;   // 192*16 = 3072
        int n = idx >> 4, k = idx & 15;
        float v = (n < HID && k < INCH) ? W0[k * HID + n] : 0.f;
        __half h, l; split_h(v, h, l);
        g_W0th[idx] = h; g_W0tl[idx] = l;
    } else if (b < 444) {
        int q = b - 12;
        int L = q / 144;
        int idx = (q - L * 144) * 256 + t;
        int n = idx / 192, k = idx % 192;
        float v = (n < HID && k < HID) ? Wh[(size_t)L * HID * HID + k * HID + n] : 0.f;
        __half h, l; split_h(v, h, l);
        g_Whth[L * 36864 + idx] = h; g_Whtl[L * 36864 + idx] = l;
    } else if (b < 1020) {
        int idx = (b - 444) * 256 + t;
        int n = idx / 768, k = idx % 768;
        int layer = k / 192, c = k % 192;
        float v = (n < HID && c < HID) ? Wjk[(size_t)(layer * HID + c) * HID + n] : 0.f;
        g_Wjkth[idx] = __float2half_rn(v);
    } else if (b < 1023) {
        int i = (b - 1020) * 256 + t;
        if (i < 4 * HID) {
            float sc = gamma[i] * rsqrtf(var[i] + 1e-5f);
            g_bnscale[i] = sc;
            g_bnshift[i] = beta[i] - mean[i] * sc;
        }
    } else {
        int i = (b - 1023) * 256 + t;
        if (i < G * HID) g_pool[i] = 0x007FFFFFu;    // enc(-inf)
    }
}

__global__ void k_scan_blk(int N) {
    __shared__ int sh[256];
    int i = blockIdx.x * 256 + threadIdx.x;
    int v = (i < N) ? g_cnt[i] : 0;
    sh[threadIdx.x] = v;
    __syncthreads();
    for (int o = 1; o < 256; o <<= 1) {
        int a = (threadIdx.x >= o) ? sh[threadIdx.x - o] : 0;
        __syncthreads();
        sh[threadIdx.x] += a;
        __syncthreads();
    }
    if (i < N) g_part[i] = sh[threadIdx.x] - v;
    if (threadIdx.x == 255) g_bsum[blockIdx.x] = sh[255];
}
__global__ void k_scan_add(int N, int SB) {
    __shared__ int sh[128];
    int t = threadIdx.x;
    if (t < 128) sh[t] = (t < SB) ? g_bsum[t] : 0;
    __syncthreads();
    for (int o = 1; o < 128; o <<= 1) {
        int a = (t >= o && t < 128) ? sh[t - o] : 0;
        __syncthreads();
        if (t < 128) sh[t] += a;
        __syncthreads();
    }
    int i = blockIdx.x * 256 + t;
    if (i >= N) return;
    int pre = sh[blockIdx.x] - g_bsum[blockIdx.x];
    int off = g_part[i] + pre;
    int c = g_cnt[i];
    g_cnt[i] = 0;
    g_offs[i] = off;
    if (i == N - 1) g_offs[N] = off + c;
    g_dis[i] = rsqrtf((float)c + 1.0f);
}
// atomic-free fill: slot = offs[dst] + precomputed rank
__global__ void k_fill(const int* __restrict__ ei, int E) {
    int e = blockIdx.x * blockDim.x + threadIdx.x;
    if (e >= E) return;
    int s = ei[e], d = ei[E + e];
    int p = g_offs[d] + g_erank[e];
    g_csr[p] = make_int2(s, __float_as_int(g_dis[s]));
}

// aggregate raw x (9 ch) -> fp16 A0 [N x 16]
__global__ void k_aggregate_x(const float* __restrict__ x, int N) {
    int warp = (blockIdx.x * blockDim.x + threadIdx.x) >> 5;
    int lane = threadIdx.x & 31;
    if (warp >= N) return;
    int n = warp;
    int s0 = g_offs[n], s1 = g_offs[n + 1];
    float acc[INCH];
#pragma unroll
    for (int c = 0; c < INCH; c++) acc[c] = 0.f;
    for (int e = s0 + lane; e < s1; e += 32) {
        int2 ed = g_csr[e];
        float w = __int_as_float(ed.y);
#pragma unroll
        for (int c = 0; c < INCH; c++) acc[c] += w * x[ed.x * INCH + c];
    }
#pragma unroll
    for (int c = 0; c < INCH; c++)
#pragma unroll
        for (int o = 16; o; o >>= 1)
            acc[c] += __shfl_xor_sync(0xffffffffu, acc[c], o);
    if (lane == 0) {
        float dn = g_dis[n];
#pragma unroll
        for (int c = 0; c < INCH; c++) {
            float v = dn * acc[c] + dn * dn * x[n * INCH + c];
            g_A0[n * 16 + c] = __float2half_rn(v);
        }
    }
    if (lane < 16 - INCH)
        g_A0[n * 16 + INCH + lane] = __float2half_rn(0.f);
}

// ---------------- fp16 GEMM: CTA tile 256x64, single-wave grid ---------------
// stage (bytes): sA 0 (256x144 = 36864), sBh 36864 (9216), sBl 46080 (9216)
#define STG 55296
#define SMEM_BYTES (2 * STG)
#define SBH_OFF 36864u
#define SBL_DELTA 9216u    // sBl - sBh (bytes)

__device__ __forceinline__ void ld_stage(
    uint32_t smb,
    const __half* __restrict__ A, int lda,
    const __half* __restrict__ Bh, const __half* __restrict__ Bl, int ldb,
    int rowBase, int colBase, int k0, int Nrows, int tid, int dual, int kw16) {
    if (kw16) {
        // A: 256 rows x 16 halves = 512 16B-chunks -> 2 iters
#pragma unroll
        for (int s = 0; s < 2; s++) {
            int idx = tid + s * 256;
            int r = idx >> 1, j = idx & 1;
            int gr = rowBase + r;
            int sz = (gr < Nrows) ? 16 : 0;
            int grc = min(gr, Nrows - 1);
            CP16(smb + r * 144 + j * 16, A + (size_t)grc * lda + j * 8, sz);
        }
        // B: 64 rows x 16 halves = 128 chunks
        if (tid < 128) {
            int n = tid >> 1, jb = tid & 1;
            size_t go = (size_t)(colBase + n) * ldb + jb * 8;
            uint32_t d = smb + SBH_OFF + n * 144 + jb * 16;
            CP16(d, Bh + go, 16);
            if (dual) CP16(d + SBL_DELTA, Bl + go, 16);
        }
        return;
    }
    // A: 256 rows x 64 halves = 2048 chunks -> 8 iters
#pragma unroll
    for (int s = 0; s < 8; s++) {
        int idx = tid + s * 256;
        int r = idx >> 3, j = idx & 7;
        int gr = rowBase + r;
        int sz = (gr < Nrows) ? 16 : 0;
        int grc = min(gr, Nrows - 1);
        size_t go = (size_t)grc * lda + k0 + j * 8;
        CP16(smb + r * 144 + j * 16, A + go, sz);
    }
    // B: 64 rows x 64 halves = 512 chunks -> 2 iters
#pragma unroll
    for (int s = 0; s < 2; s++) {
        int idx = tid + s * 256;
        int n = idx >> 3, j = idx & 7;
        size_t go = (size_t)(colBase + n) * ldb + k0 + j * 8;
        uint32_t d = smb + SBH_OFF + n * 144 + j * 16;
        CP16(d, Bh + go, 16);
        if (dual) CP16(d + SBL_DELTA, Bl + go, 16);
    }
}

// warp layout: 8 warps, wm = w&3 (64-row groups), wn = w>>2 (32-col groups)
// warp tile 64x32 -> mf 0..3 (16-row frags), nf 0..3 (8-col frags)
// mode 2: bias+bn+relu -> fp16 half2    mode 3: bias -> smem-staged max-pool
__global__ void __launch_bounds__(256, 2)
k_mma(const __half* __restrict__ A, int lda,
      const __half* __restrict__ Bh, const __half* __restrict__ Bl, int ldb,
      int Nrows, int Ktiles,
      __half* __restrict__ O,
      const float* __restrict__ bias, const float* __restrict__ scale,
      const float* __restrict__ shift,
      const int* __restrict__ batch, unsigned* __restrict__ pool,
      int mode, int dual, int ksteps, int kw16) {
    extern __shared__ __align__(16) char smch[];
    uint32_t sb = smem_u32(smch);

    int tid = threadIdx.x, lane = tid & 31, w = tid >> 5;
    int wm = w & 3, wn = w >> 2;
    int rowBase = blockIdx.y * 256, colBase = blockIdx.x * 64;

    float acc[4][4][4];
#pragma unroll
    for (int i = 0; i < 4; i++)
#pragma unroll
        for (int j = 0; j < 4; j++)
#pragma unroll
            for (int q = 0; q < 4; q++) acc[i][j][q] = 0.f;

    const uint32_t offA = (uint32_t)((wm * 64 + (lane & 15)) * 72 + (lane >> 4) * 8) << 1;
    const uint32_t offB = SBH_OFF +
        ((uint32_t)((wn * 32 + (lane & 7) + ((lane >> 4) << 3)) * 72 + ((lane >> 3) & 1) * 8) << 1);
    const uint32_t B_LO = SBL_DELTA, MF = 2304;   // bytes

    ld_stage(sb, A, lda, Bh, Bl, ldb, rowBase, colBase, 0, Nrows, tid, dual, kw16);
    CP_COMMIT();

    for (int kt = 0; kt < Ktiles; kt++) {
        uint32_t stb = sb + (uint32_t)(kt & 1) * STG;
        if (kt + 1 < Ktiles) {
            ld_stage(sb + (uint32_t)((kt + 1) & 1) * STG, A, lda, Bh, Bl, ldb,
                     rowBase, colBase, (kt + 1) * 64, Nrows, tid, dual, kw16);
            CP_COMMIT();
            CP_WAIT1();
        } else {
            CP_WAIT0();
        }
        __syncthreads();

        uint32_t aA = stb + offA;
        uint32_t aB = stb + offB;
        for (int ks = 0; ks < ksteps; ks++) {
            uint32_t kso = ks * 32;
            uint32_t bh[4][2], bl[4][2];
            LDSM4(bh[0][0], bh[0][1], bh[1][0], bh[1][1], aB + kso);
            LDSM4(bh[2][0], bh[2][1], bh[3][0], bh[3][1], aB + MF + kso);
            if (dual) {
                LDSM4(bl[0][0], bl[0][1], bl[1][0], bl[1][1], aB + B_LO + kso);
                LDSM4(bl[2][0], bl[2][1], bl[3][0], bl[3][1], aB + B_LO + MF + kso);
            }
#pragma unroll
            for (int mf = 0; mf < 4; mf++) {
                uint32_t ar[4];
                LDSM4(ar[0], ar[1], ar[2], ar[3], aA + mf * MF + kso);
#pragma unroll
                for (int nf = 0; nf < 4; nf++) {
                    mma16(acc[mf][nf], ar, bh[nf]);
                    if (dual) mma16(acc[mf][nf], ar, bl[nf]);
                }
            }
        }
        __syncthreads();
    }

    int gid = lane >> 2, tig = lane & 3;
    if (mode == 2) {
#pragma unroll
        for (int mf = 0; mf < 4; mf++) {
#pragma unroll
            for (int half = 0; half < 2; half++) {
                int r = rowBase + wm * 64 + mf * 16 + gid + half * 8;
                if (r >= Nrows) continue;
#pragma unroll
                for (int nf = 0; nf < 4; nf++) {
                    int c0 = colBase + wn * 32 + nf * 8 + tig * 2;
                    float v0 = acc[mf][nf][half * 2];
                    float v1 = acc[mf][nf][half * 2 + 1];
                    float o0 = 0.f, o1 = 0.f;
                    if (c0 < HID)
                        o0 = fmaxf(fmaf(v0 + bias[c0], scale[c0], shift[c0]), 0.f);
                    if (c0 + 1 < HID)
                        o1 = fmaxf(fmaf(v1 + bias[c0 + 1], scale[c0 + 1], shift[c0 + 1]), 0.f);
                    *(__half2*)(O + (size_t)r * LDAH + c0) =
                        __halves2half2(__float2half_rn(o0), __float2half_rn(o1));
                }
            }
        }
    } else {
        // mode 3: smem-staged max-pool (batch sorted; 256-row tile spans <= 256 graphs)
        unsigned* spool = (unsigned*)smch;
        int g0 = batch[rowBase];
        int rlast = min(rowBase + 255, Nrows - 1);
        int range = batch[rlast] - g0 + 1;
        for (int i = tid; i < range * 64; i += 256) spool[i] = 0x007FFFFFu;
        __syncthreads();
#pragma unroll
        for (int mf = 0; mf < 4; mf++) {
#pragma unroll
            for (int half = 0; half < 2; half++) {
                int r = rowBase + wm * 64 + mf * 16 + gid + half * 8;
                if (r >= Nrows) continue;
                int bloc = (batch[r] - g0) * 64;
#pragma unroll
                for (int nf = 0; nf < 4; nf++) {
                    int c0 = colBase + wn * 32 + nf * 8 + tig * 2;
                    float v0 = acc[mf][nf][half * 2];
                    float v1 = acc[mf][nf][half * 2 + 1];
                    int cl = wn * 32 + nf * 8 + tig * 2;
                    if (c0 < HID)
                        atomicMax(&spool[bloc + cl], enc_f(v0 + bias[c0]));
                    if (c0 + 1 < HID)
                        atomicMax(&spool[bloc + cl + 1], enc_f(v1 + bias[c0 + 1]));
                }
            }
        }
        __syncthreads();
        for (int i = tid; i < range * 64; i += 256) {
            int bgr = i >> 6;
            int c = colBase + (i & 63);
            if (c < HID)
                atomicMax(&pool[(g0 + bgr) * HID + c], spool[i]);
        }
    }
}

// fp16 aggregation: z[n] = dn * sum_e w_e * h[src_e] + dn^2 * h[n]   (half2 lanes)
__global__ void k_agg16(const __half* __restrict__ src, int N) {
    int n = blockIdx.x;
    int c0 = threadIdx.x * 2;
    int s0 = g_offs[n], s1 = g_offs[n + 1];
    float a0 = 0.f, a1 = 0.f;
    int e = s0;
    for (; e + 4 <= s1; e += 4) {
        int2 e0 = g_csr[e],     e1 = g_csr[e + 1];
        int2 e2 = g_csr[e + 2], e3 = g_csr[e + 3];
        float2 p0 = __half22float2(*(const __half2*)(src + (size_t)e0.x * LDAH + c0));
        float2 p1 = __half22float2(*(const __half2*)(src + (size_t)e1.x * LDAH + c0));
        float2 p2 = __half22float2(*(const __half2*)(src + (size_t)e2.x * LDAH + c0));
        float2 p3 = __half22float2(*(const __half2*)(src + (size_t)e3.x * LDAH + c0));
        float w0 = __int_as_float(e0.y), w1 = __int_as_float(e1.y);
        float w2 = __int_as_float(e2.y), w3 = __int_as_float(e3.y);
        a0 += w0 * p0.x + w1 * p1.x + w2 * p2.x + w3 * p3.x;
        a1 += w0 * p0.y + w1 * p1.y + w2 * p2.y + w3 * p3.y;
    }
    for (; e < s1; ++e) {
        int2 ed = g_csr[e];
        float w = __int_as_float(ed.y);
        float2 p = __half22float2(*(const __half2*)(src + (size_t)ed.x * LDAH + c0));
        a0 += w * p.x;
        a1 += w * p.y;
    }
    float dn = g_dis[n];
    float2 self = __half22float2(*(const __half2*)(src + (size_t)n * LDAH + c0));
    float v0 = dn * a0 + dn * dn * self.x;
    float v1 = dn * a1 + dn * dn * self.y;
    *(__half2*)(g_Z + (size_t)n * LDZ + c0) = __floats2half2_rn(v0, v1);
}

__global__ void k_finalize(const float* __restrict__ Wout,
                           const float* __restrict__ bout,
                           float* __restrict__ out, int G) {
    int g = blockIdx.x, t = threadIdx.x;
    __shared__ float red[256];
    float p = 0.f;
    for (int c = t; c < HID; c += 256)
        p += dec_f(g_pool[g * HID + c]) * Wout[c];
    red[t] = p;
    __syncthreads();
    for (int o = 128; o; o >>= 1) {
        if (t < o) red[t] += red[t + o];
        __syncthreads();
    }
    if (t == 0) out[g] = red[0] + bout[0];
}

// ---------------- host launcher ----------------
extern "C" void kernel_launch(void* const* d_in, const int* in_sizes, int n_in,
                              void* d_out, int out_size) {
    const float* x     = (const float*)d_in[0];
    const int*   ei    = (const int*)  d_in[1];
    const int*   batch = (const int*)  d_in[2];
    const float* W0    = (const float*)d_in[3];
    const float* b0    = (const float*)d_in[4];
    const float* W_h   = (const float*)d_in[5];
    const float* b_h   = (const float*)d_in[6];
    const float* bn_g  = (const float*)d_in[7];
    const float* bn_b  = (const float*)d_in[8];
    const float* bn_m  = (const float*)d_in[9];
    const float* bn_v  = (const float*)d_in[10];
    const float* W_jk  = (const float*)d_in[11];
    const float* b_jk  = (const float*)d_in[12];
    const float* W_out = (const float*)d_in[13];
    const float* b_out = (const float*)d_in[14];
    float* out = (float*)d_out;

    int N = in_sizes[0] / INCH;
    int E = in_sizes[1] / 2;
    int G = out_size;
    int SB = (N + 255) / 256;
    int EB = (E + 255) / 256;
    int poolBlks = (G * HID + 255) / 256;

    cudaFuncSetAttribute(k_mma, cudaFuncAttributeMaxDynamicSharedMemorySize, SMEM_BYTES);

    __half *a0, *axs, *zz, *w0h, *w0l, *whh, *whl, *wjh;
    cudaGetSymbolAddress((void**)&a0,  g_A0);
    cudaGetSymbolAddress((void**)&axs, g_Axs);
    cudaGetSymbolAddress((void**)&zz,  g_Z);
    cudaGetSymbolAddress((void**)&w0h, g_W0th);
    cudaGetSymbolAddress((void**)&w0l, g_W0tl);
    cudaGetSymbolAddress((void**)&whh, g_Whth);
    cudaGetSymbolAddress((void**)&whl, g_Whtl);
    cudaGetSymbolAddress((void**)&wjh, g_Wjkth);
    float *bns, *bnh;
    cudaGetSymbolAddress((void**)&bns, g_bnscale);
    cudaGetSymbolAddress((void**)&bnh, g_bnshift);
    unsigned* pool;
    cudaGetSymbolAddress((void**)&pool, g_pool);

    k_prep<<<EB + 1023 + poolBlks, 256>>>(ei, E, EB, W0, W_h, W_jk,
                                          bn_g, bn_b, bn_m, bn_v, G);
    k_scan_blk<<<SB, 256>>>(N);
    k_scan_add<<<SB, 256>>>(N, SB);
    k_fill<<<(E + 255) / 256, 256>>>(ei, E);
    k_aggregate_x<<<(N * 32 + 255) / 256, 256>>>(x, N);

    dim3 grid(3, (N + 255) / 256);   // 294 CTAs -> single wave at 2 CTAs/SM

    // layer 0: (Âx)@W0 -> bias+bn0+relu -> fp16 concat cols [0,192)  (16-wide K)
    k_mma<<<grid, 256, SMEM_BYTES>>>(a0, 16, w0h, w0l, 16, N, 1,
                                     axs, b0, bns, bnh,
                                     (const int*)0, (unsigned*)0, 2, 1, 1, 1);
    // hidden layers 1..3: aggregate fp16 activations first, then GEMM+epilogue
    for (int i = 1; i <= 3; i++) {
        k_agg16<<<N, 96>>>(axs + (size_t)(i - 1) * 192, N);
        k_mma<<<grid, 256, SMEM_BYTES>>>(zz, LDZ,
                                         whh + (size_t)(i - 1) * 36864,
                                         whl + (size_t)(i - 1) * 36864, 192,
                                         N, 3,
                                         axs + (size_t)i * 192,
                                         b_h + (size_t)(i - 1) * HID,
                                         bns + i * HID, bnh + i * HID,
                                         (const int*)0, (unsigned*)0, 2, 1, 4, 0);
    }
    // JK GEMM fused with smem-staged max-pool (hi-only weights: last layer)
    k_mma<<<grid, 256, SMEM_BYTES>>>(axs, LDAH, wjh, wjh, 768, N, 12,
                                     (__half*)0,
                                     b_jk, (const float*)0, (const float*)0,
                                     batch, pool, 3, 0, 4, 0);

    k_finalize<<<G, 256>>>(W_out, b_out, out, G);
}

// round 13
// speedup vs baseline: 1.4213x; 1.0120x over previous
#include <cuda_runtime.h>
#include <cuda_fp16.h>
#include <cstdint>
#include <math.h>

#define NMAX   25000
#define EMAX   400000
#define GMAX   1000
#define HID    185
#define INCH   9
#define LDAH   768      // padded concat width (4*192)
#define LDZ    192      // aggregated-activation row stride

// ---------------- scratch ----------------
__device__ int      g_cnt[NMAX];          // BSS zero; self-cleaned each call
__device__ int      g_part[NMAX];
__device__ int      g_bsum[128];
__device__ int      g_offs[NMAX + 1];
__device__ float    g_dis[NMAX];
__device__ int      g_erank[EMAX];
__device__ __align__(16) int2 g_csr[EMAX];   // (src, weight bits)
__device__ __align__(16) __half g_A0[NMAX * 16];
__device__ __align__(16) __half g_Axs[NMAX * LDAH];
__device__ __align__(16) __half g_Z[NMAX * LDZ];
__device__ __align__(16) __half g_W0th[192 * 16];
__device__ __align__(16) __half g_W0tl[192 * 16];
__device__ __align__(16) __half g_Whth[3 * 192 * 192];
__device__ __align__(16) __half g_Wjkth[192 * 768];
__device__ unsigned g_pool[GMAX * HID];
__device__ float    g_bnscale[4 * HID];
__device__ float    g_bnshift[4 * HID];

// ---------------- helpers ----------------
__device__ __forceinline__ unsigned enc_f(float f) {
    unsigned u = __float_as_uint(f);
    return (u & 0x80000000u) ? ~u : (u | 0x80000000u);
}
__device__ __forceinline__ float dec_f(unsigned e) {
    return (e & 0x80000000u) ? __uint_as_float(e & 0x7FFFFFFFu) : __uint_as_float(~e);
}
__device__ __forceinline__ void split_h(float v, __half& h, __half& l) {
    h = __float2half_rn(v);
    l = __float2half_rn(v - __half2float(h));
}
__device__ __forceinline__ uint32_t smem_u32(const void* p) {
    uint32_t a;
    asm("{ .reg .u64 t; cvta.to.shared.u64 t, %1; cvt.u32.u64 %0, t; }" : "=r"(a) : "l"(p));
    return a;
}
#define LDSM4(r0, r1, r2, r3, addr) \
    asm volatile("ldmatrix.sync.aligned.m8n8.x4.shared.b16 {%0,%1,%2,%3}, [%4];" \
        : "=r"(r0), "=r"(r1), "=r"(r2), "=r"(r3) : "r"(addr))
__device__ __forceinline__ void mma16(float* c, const uint32_t* a, const uint32_t* b) {
    asm volatile("mma.sync.aligned.m16n8k16.row.col.f32.f16.f16.f32 "
        "{%0,%1,%2,%3}, {%4,%5,%6,%7}, {%8,%9}, {%0,%1,%2,%3};"
        : "+f"(c[0]), "+f"(c[1]), "+f"(c[2]), "+f"(c[3])
        : "r"(a[0]), "r"(a[1]), "r"(a[2]), "r"(a[3]), "r"(b[0]), "r"(b[1]));
}
#define CP16(dst, src, sz) \
    asm volatile("cp.async.cg.shared.global [%0], [%1], 16, %2;" \
        :: "r"(dst), "l"(src), "r"(sz) : "memory")
#define CP_COMMIT() asm volatile("cp.async.commit_group;" ::: "memory")
#define CP_WAIT0()  asm volatile("cp.async.wait_group 0;" ::: "memory")
#define CP_WAIT1()  asm volatile("cp.async.wait_group 1;" ::: "memory")

// ---------------- merged: edge count+rank + weight prep + BN fold + pool init
// blocks: [0,EB) count | [EB,+12) W0 | [+12,+444) Wh(hi) | [+444,+1020) Wjk
//         [+1020,+1023) bn | [+1023, +1023+poolBlks) pool
__global__ void k_prep(const int* __restrict__ ei, int E, int EB,
                       const float* __restrict__ W0, const float* __restrict__ Wh,
                       const float* __restrict__ Wjk,
                       const float* __restrict__ gamma, const float* __restrict__ beta,
                       const float* __restrict__ mean, const float* __restrict__ var,
                       int G) {
    int t = threadIdx.x;
    if (blockIdx.x < EB) {
        int e = blockIdx.x * 256 + t;
        if (e < E) g_erank[e] = atomicAdd(&g_cnt[ei[E + e]], 1);
        return;
    }
    int b = blockIdx.x - EB;
    if (b < 12) {
        int idx = b * 256 + t;   // 192*16 = 3072
        int n = idx >> 4, k = idx & 15;
        float v = (n < HID && k < INCH) ? W0[k * HID + n] : 0.f;
        __half h, l; split_h(v, h, l);
        g_W0th[idx] = h; g_W0tl[idx] = l;
    } else if (b < 444) {
        int q = b - 12;
        int L = q / 144;
        int idx = (q - L * 144) * 256 + t;
        int n = idx / 192, k = idx % 192;
        float v = (n < HID && k < HID) ? Wh[(size_t)L * HID * HID + k * HID + n] : 0.f;
        g_Whth[L * 36864 + idx] = __float2half_rn(v);
    } else if (b < 1020) {
        int idx = (b - 444) * 256 + t;
        int n = idx / 768, k = idx % 768;
        int layer = k / 192, c = k % 192;
        float v = (n < HID && c < HID) ? Wjk[(size_t)(layer * HID + c) * HID + n] : 0.f;
        g_Wjkth[idx] = __float2half_rn(v);
    } else if (b < 1023) {
        int i = (b - 1020) * 256 + t;
        if (i < 4 * HID) {
            float sc = gamma[i] * rsqrtf(var[i] + 1e-5f);
            g_bnscale[i] = sc;
            g_bnshift[i] = beta[i] - mean[i] * sc;
        }
    } else {
        int i = (b - 1023) * 256 + t;
        if (i < G * HID) g_pool[i] = 0x007FFFFFu;    // enc(-inf)
    }
}

__global__ void k_scan_blk(int N) {
    __shared__ int sh[256];
    int i = blockIdx.x * 256 + threadIdx.x;
    int v = (i < N) ? g_cnt[i] : 0;
    sh[threadIdx.x] = v;
    __syncthreads();
    for (int o = 1; o < 256; o <<= 1) {
        int a = (threadIdx.x >= o) ? sh[threadIdx.x - o] : 0;
        __syncthreads();
        sh[threadIdx.x] += a;
        __syncthreads();
    }
    if (i < N) g_part[i] = sh[threadIdx.x] - v;
    if (threadIdx.x == 255) g_bsum[blockIdx.x] = sh[255];
}
__global__ void k_scan_add(int N, int SB) {
    __shared__ int sh[128];
    int t = threadIdx.x;
    if (t < 128) sh[t] = (t < SB) ? g_bsum[t] : 0;
    __syncthreads();
    for (int o = 1; o < 128; o <<= 1) {
        int a = (t >= o && t < 128) ? sh[t - o] : 0;
        __syncthreads();
        if (t < 128) sh[t] += a;
        __syncthreads();
    }
    int i = blockIdx.x * 256 + t;
    if (i >= N) return;
    int pre = sh[blockIdx.x] - g_bsum[blockIdx.x];
    int off = g_part[i] + pre;
    int c = g_cnt[i];
    g_cnt[i] = 0;
    g_offs[i] = off;
    if (i == N - 1) g_offs[N] = off + c;
    g_dis[i] = rsqrtf((float)c + 1.0f);
}
// atomic-free fill: slot = offs[dst] + precomputed rank
__global__ void k_fill(const int* __restrict__ ei, int E) {
    int e = blockIdx.x * blockDim.x + threadIdx.x;
    if (e >= E) return;
    int s = ei[e], d = ei[E + e];
    int p = g_offs[d] + g_erank[e];
    g_csr[p] = make_int2(s, __float_as_int(g_dis[s]));
}

// aggregate raw x (9 ch) -> fp16 A0 [N x 16]
__global__ void k_aggregate_x(const float* __restrict__ x, int N) {
    int warp = (blockIdx.x * blockDim.x + threadIdx.x) >> 5;
    int lane = threadIdx.x & 31;
    if (warp >= N) return;
    int n = warp;
    int s0 = g_offs[n], s1 = g_offs[n + 1];
    float acc[INCH];
#pragma unroll
    for (int c = 0; c < INCH; c++) acc[c] = 0.f;
    for (int e = s0 + lane; e < s1; e += 32) {
        int2 ed = g_csr[e];
        float w = __int_as_float(ed.y);
#pragma unroll
        for (int c = 0; c < INCH; c++) acc[c] += w * x[ed.x * INCH + c];
    }
#pragma unroll
    for (int c = 0; c < INCH; c++)
#pragma unroll
        for (int o = 16; o; o >>= 1)
            acc[c] += __shfl_xor_sync(0xffffffffu, acc[c], o);
    if (lane == 0) {
        float dn = g_dis[n];
#pragma unroll
        for (int c = 0; c < INCH; c++) {
            float v = dn * acc[c] + dn * dn * x[n * INCH + c];
            g_A0[n * 16 + c] = __float2half_rn(v);
        }
    }
    if (lane < 16 - INCH)
        g_A0[n * 16 + INCH + lane] = __float2half_rn(0.f);
}

// ---------------- fp16 GEMM: CTA tile 256x64, single-wave grid ---------------
// stage (bytes): sA 0 (256x144 = 36864), sBh 36864 (9216), sBl 46080 (9216)
#define STG 55296
#define SMEM_BYTES (2 * STG)
#define SBH_OFF 36864u
#define SBL_DELTA 9216u    // sBl - sBh (bytes)

__device__ __forceinline__ void ld_stage(
    uint32_t smb,
    const __half* __restrict__ A, int lda,
    const __half* __restrict__ Bh, const __half* __restrict__ Bl, int ldb,
    int rowBase, int colBase, int k0, int Nrows, int tid, int dual, int kw16) {
    if (kw16) {
#pragma unroll
        for (int s = 0; s < 2; s++) {
            int idx = tid + s * 256;
            int r = idx >> 1, j = idx & 1;
            int gr = rowBase + r;
            int sz = (gr < Nrows) ? 16 : 0;
            int grc = min(gr, Nrows - 1);
            CP16(smb + r * 144 + j * 16, A + (size_t)grc * lda + j * 8, sz);
        }
        if (tid < 128) {
            int n = tid >> 1, jb = tid & 1;
            size_t go = (size_t)(colBase + n) * ldb + jb * 8;
            uint32_t d = smb + SBH_OFF + n * 144 + jb * 16;
            CP16(d, Bh + go, 16);
            if (dual) CP16(d + SBL_DELTA, Bl + go, 16);
        }
        return;
    }
#pragma unroll
    for (int s = 0; s < 8; s++) {
        int idx = tid + s * 256;
        int r = idx >> 3, j = idx & 7;
        int gr = rowBase + r;
        int sz = (gr < Nrows) ? 16 : 0;
        int grc = min(gr, Nrows - 1);
        size_t go = (size_t)grc * lda + k0 + j * 8;
        CP16(smb + r * 144 + j * 16, A + go, sz);
    }
#pragma unroll
    for (int s = 0; s < 2; s++) {
        int idx = tid + s * 256;
        int n = idx >> 3, j = idx & 7;
        size_t go = (size_t)(colBase + n) * ldb + k0 + j * 8;
        uint32_t d = smb + SBH_OFF + n * 144 + j * 16;
        CP16(d, Bh + go, 16);
        if (dual) CP16(d + SBL_DELTA, Bl + go, 16);
    }
}

// warp layout: 8 warps, wm = w&3 (64-row groups), wn = w>>2 (32-col groups)
// mode 2: bias+bn+relu -> fp16 half2    mode 3: bias -> smem-staged max-pool
__global__ void __launch_bounds__(256, 2)
k_mma(const __half* __restrict__ A, int lda,
      const __half* __restrict__ Bh, const __half* __restrict__ Bl, int ldb,
      int Nrows, int Ktiles,
      __half* __restrict__ O,
      const float* __restrict__ bias, const float* __restrict__ scale,
      const float* __restrict__ shift,
      const int* __restrict__ batch, unsigned* __restrict__ pool,
      int mode, int dual, int ksteps, int kw16) {
    extern __shared__ __align__(16) char smch[];
    uint32_t sb = smem_u32(smch);

    int tid = threadIdx.x, lane = tid & 31, w = tid >> 5;
    int wm = w & 3, wn = w >> 2;
    int rowBase = blockIdx.y * 256, colBase = blockIdx.x * 64;

    float acc[4][4][4];
#pragma unroll
    for (int i = 0; i < 4; i++)
#pragma unroll
        for (int j = 0; j < 4; j++)
#pragma unroll
            for (int q = 0; q < 4; q++) acc[i][j][q] = 0.f;

    const uint32_t offA = (uint32_t)((wm * 64 + (lane & 15)) * 72 + (lane >> 4) * 8) << 1;
    const uint32_t offB = SBH_OFF +
        ((uint32_t)((wn * 32 + (lane & 7) + ((lane >> 4) << 3)) * 72 + ((lane >> 3) & 1) * 8) << 1);
    const uint32_t B_LO = SBL_DELTA, MF = 2304;   // bytes

    ld_stage(sb, A, lda, Bh, Bl, ldb, rowBase, colBase, 0, Nrows, tid, dual, kw16);
    CP_COMMIT();

    for (int kt = 0; kt < Ktiles; kt++) {
        uint32_t stb = sb + (uint32_t)(kt & 1) * STG;
        if (kt + 1 < Ktiles) {
            ld_stage(sb + (uint32_t)((kt + 1) & 1) * STG, A, lda, Bh, Bl, ldb,
                     rowBase, colBase, (kt + 1) * 64, Nrows, tid, dual, kw16);
            CP_COMMIT();
            CP_WAIT1();
        } else {
            CP_WAIT0();
        }
        __syncthreads();

        uint32_t aA = stb + offA;
        uint32_t aB = stb + offB;
        for (int ks = 0; ks < ksteps; ks++) {
            uint32_t kso = ks * 32;
            uint32_t bh[4][2], bl[4][2];
            LDSM4(bh[0][0], bh[0][1], bh[1][0], bh[1][1], aB + kso);
            LDSM4(bh[2][0], bh[2][1], bh[3][0], bh[3][1], aB + MF + kso);
            if (dual) {
                LDSM4(bl[0][0], bl[0][1], bl[1][0], bl[1][1], aB + B_LO + kso);
                LDSM4(bl[2][0], bl[2][1], bl[3][0], bl[3][1], aB + B_LO + MF + kso);
            }
#pragma unroll
            for (int mf = 0; mf < 4; mf++) {
                uint32_t ar[4];
                LDSM4(ar[0], ar[1], ar[2], ar[3], aA + mf * MF + kso);
#pragma unroll
                for (int nf = 0; nf < 4; nf++) {
                    mma16(acc[mf][nf], ar, bh[nf]);
                    if (dual) mma16(acc[mf][nf], ar, bl[nf]);
                }
            }
        }
        __syncthreads();
    }

    int gid = lane >> 2, tig = lane & 3;
    if (mode == 2) {
#pragma unroll
        for (int mf = 0; mf < 4; mf++) {
#pragma unroll
            for (int half = 0; half < 2; half++) {
                int r = rowBase + wm * 64 + mf * 16 + gid + half * 8;
                if (r >= Nrows) continue;
#pragma unroll
                for (int nf = 0; nf < 4; nf++) {
                    int c0 = colBase + wn * 32 + nf * 8 + tig * 2;
                    float v0 = acc[mf][nf][half * 2];
                    float v1 = acc[mf][nf][half * 2 + 1];
                    float o0 = 0.f, o1 = 0.f;
                    if (c0 < HID)
                        o0 = fmaxf(fmaf(v0 + bias[c0], scale[c0], shift[c0]), 0.f);
                    if (c0 + 1 < HID)
                        o1 = fmaxf(fmaf(v1 + bias[c0 + 1], scale[c0 + 1], shift[c0 + 1]), 0.f);
                    *(__half2*)(O + (size_t)r * LDAH + c0) =
                        __halves2half2(__float2half_rn(o0), __float2half_rn(o1));
                }
            }
        }
    } else {
        // mode 3: smem-staged max-pool (batch sorted; 256-row tile spans <= 256 graphs)
        unsigned* spool = (unsigned*)smch;
        int g0 = batch[rowBase];
        int rlast = min(rowBase + 255, Nrows - 1);
        int range = batch[rlast] - g0 + 1;
        for (int i = tid; i < range * 64; i += 256) spool[i] = 0x007FFFFFu;
        __syncthreads();
#pragma unroll
        for (int mf = 0; mf < 4; mf++) {
#pragma unroll
            for (int half = 0; half < 2; half++) {
                int r = rowBase + wm * 64 + mf * 16 + gid + half * 8;
                if (r >= Nrows) continue;
                int bloc = (batch[r] - g0) * 64;
#pragma unroll
                for (int nf = 0; nf < 4; nf++) {
                    int c0 = colBase + wn * 32 + nf * 8 + tig * 2;
                    float v0 = acc[mf][nf][half * 2];
                    float v1 = acc[mf][nf][half * 2 + 1];
                    int cl = wn * 32 + nf * 8 + tig * 2;
                    if (c0 < HID)
                        atomicMax(&spool[bloc + cl], enc_f(v0 + bias[c0]));
                    if (c0 + 1 < HID)
                        atomicMax(&spool[bloc + cl + 1], enc_f(v1 + bias[c0 + 1]));
                }
            }
        }
        __syncthreads();
        for (int i = tid; i < range * 64; i += 256) {
            int bgr = i >> 6;
            int c = colBase + (i & 63);
            if (c < HID)
                atomicMax(&pool[(g0 + bgr) * HID + c], spool[i]);
        }
    }
}

// fp16 aggregation: z[n] = dn * sum_e w_e * h[src_e] + dn^2 * h[n]   (half2 lanes)
__global__ void k_agg16(const __half* __restrict__ src, int N) {
    int n = blockIdx.x;
    int c0 = threadIdx.x * 2;
    int s0 = g_offs[n], s1 = g_offs[n + 1];
    float a0 = 0.f, a1 = 0.f;
    int e = s0;
    for (; e + 4 <= s1; e += 4) {
        int2 e0 = g_csr[e],     e1 = g_csr[e + 1];
        int2 e2 = g_csr[e + 2], e3 = g_csr[e + 3];
        float2 p0 = __half22float2(*(const __half2*)(src + (size_t)e0.x * LDAH + c0));
        float2 p1 = __half22float2(*(const __half2*)(src + (size_t)e1.x * LDAH + c0));
        float2 p2 = __half22float2(*(const __half2*)(src + (size_t)e2.x * LDAH + c0));
        float2 p3 = __half22float2(*(const __half2*)(src + (size_t)e3.x * LDAH + c0));
        float w0 = __int_as_float(e0.y), w1 = __int_as_float(e1.y);
        float w2 = __int_as_float(e2.y), w3 = __int_as_float(e3.y);
        a0 += w0 * p0.x + w1 * p1.x + w2 * p2.x + w3 * p3.x;
        a1 += w0 * p0.y + w1 * p1.y + w2 * p2.y + w3 * p3.y;
    }
    for (; e < s1; ++e) {
        int2 ed = g_csr[e];
        float w = __int_as_float(ed.y);
        float2 p = __half22float2(*(const __half2*)(src + (size_t)ed.x * LDAH + c0));
        a0 += w * p.x;
        a1 += w * p.y;
    }
    float dn = g_dis[n];
    float2 self = __half22float2(*(const __half2*)(src + (size_t)n * LDAH + c0));
    float v0 = dn * a0 + dn * dn * self.x;
    float v1 = dn * a1 + dn * dn * self.y;
    *(__half2*)(g_Z + (size_t)n * LDZ + c0) = __floats2half2_rn(v0, v1);
}

__global__ void k_finalize(const float* __restrict__ Wout,
                           const float* __restrict__ bout,
                           float* __restrict__ out, int G) {
    int g = blockIdx.x, t = threadIdx.x;
    __shared__ float red[256];
    float p = 0.f;
    for (int c = t; c < HID; c += 256)
        p += dec_f(g_pool[g * HID + c]) * Wout[c];
    red[t] = p;
    __syncthreads();
    for (int o = 128; o; o >>= 1) {
        if (t < o) red[t] += red[t + o];
        __syncthreads();
    }
    if (t == 0) out[g] = red[0] + bout[0];
}

// ---------------- host launcher ----------------
extern "C" void kernel_launch(void* const* d_in, const int* in_sizes, int n_in,
                              void* d_out, int out_size) {
    const float* x     = (const float*)d_in[0];
    const int*   ei    = (const int*)  d_in[1];
    const int*   batch = (const int*)  d_in[2];
    const float* W0    = (const float*)d_in[3];
    const float* b0    = (const float*)d_in[4];
    const float* W_h   = (const float*)d_in[5];
    const float* b_h   = (const float*)d_in[6];
    const float* bn_g  = (const float*)d_in[7];
    const float* bn_b  = (const float*)d_in[8];
    const float* bn_m  = (const float*)d_in[9];
    const float* bn_v  = (const float*)d_in[10];
    const float* W_jk  = (const float*)d_in[11];
    const float* b_jk  = (const float*)d_in[12];
    const float* W_out = (const float*)d_in[13];
    const float* b_out = (const float*)d_in[14];
    float* out = (float*)d_out;

    int N = in_sizes[0] / INCH;
    int E = in_sizes[1] / 2;
    int G = out_size;
    int SB = (N + 255) / 256;
    int EB = (E + 255) / 256;
    int poolBlks = (G * HID + 255) / 256;

    cudaFuncSetAttribute(k_mma, cudaFuncAttributeMaxDynamicSharedMemorySize, SMEM_BYTES);

    __half *a0, *axs, *zz, *w0h, *w0l, *whh, *wjh;
    cudaGetSymbolAddress((void**)&a0,  g_A0);
    cudaGetSymbolAddress((void**)&axs, g_Axs);
    cudaGetSymbolAddress((void**)&zz,  g_Z);
    cudaGetSymbolAddress((void**)&w0h, g_W0th);
    cudaGetSymbolAddress((void**)&w0l, g_W0tl);
    cudaGetSymbolAddress((void**)&whh, g_Whth);
    cudaGetSymbolAddress((void**)&wjh, g_Wjkth);
    float *bns, *bnh;
    cudaGetSymbolAddress((void**)&bns, g_bnscale);
    cudaGetSymbolAddress((void**)&bnh, g_bnshift);
    unsigned* pool;
    cudaGetSymbolAddress((void**)&pool, g_pool);

    k_prep<<<EB + 1023 + poolBlks, 256>>>(ei, E, EB, W0, W_h, W_jk,
                                          bn_g, bn_b, bn_m, bn_v, G);
    k_scan_blk<<<SB, 256>>>(N);
    k_scan_add<<<SB, 256>>>(N, SB);
    k_fill<<<(E + 255) / 256, 256>>>(ei, E);
    k_aggregate_x<<<(N * 32 + 255) / 256, 256>>>(x, N);

    dim3 grid(3, (N + 255) / 256);   // 294 CTAs -> single wave at 2 CTAs/SM

    // layer 0: (Âx)@W0 -> bias+bn0+relu -> fp16 concat cols [0,192)  (16-wide K)
    // keep dual here: x values span a wide range; it's nearly free (1 k-step)
    k_mma<<<grid, 256, SMEM_BYTES>>>(a0, 16, w0h, w0l, 16, N, 1,
                                     axs, b0, bns, bnh,
                                     (const int*)0, (unsigned*)0, 2, 1, 1, 1);
    // hidden layers 1..3: aggregate fp16 activations first, then GEMM (single fp16 weights)
    for (int i = 1; i <= 3; i++) {
        k_agg16<<<N, 96>>>(axs + (size_t)(i - 1) * 192, N);
        k_mma<<<grid, 256, SMEM_BYTES>>>(zz, LDZ,
                                         whh + (size_t)(i - 1) * 36864,
                                         whh + (size_t)(i - 1) * 36864, 192,
                                         N, 3,
                                         axs + (size_t)i * 192,
                                         b_h + (size_t)(i - 1) * HID,
                                         bns + i * HID, bnh + i * HID,
                                         (const int*)0, (unsigned*)0, 2, 0, 4, 0);
    }
    // JK GEMM fused with smem-staged max-pool (single fp16 weights)
    k_mma<<<grid, 256, SMEM_BYTES>>>(axs, LDAH, wjh, wjh, 768, N, 12,
                                     (__half*)0,
                                     b_jk, (const float*)0, (const float*)0,
                                     batch, pool, 3, 0, 4, 0);

    k_finalize<<<G, 256>>>(W_out, b_out, out, G);
}